// round 2
// baseline (speedup 1.0000x reference)
#include <cuda_runtime.h>
#include <math.h>

// Problem dims
#define B   64
#define T   100
#define D   75
#define H   1024
#define H2  2048
#define G3  3072
#define G6  6144
#define BT  6400   // B*T

// ---------------- scratch (device globals; no allocation) ----------------
__device__ float g_xg[(size_t)BT * G6];  // precomputed input gates (both dirs)
__device__ float g_ya[(size_t)BT * H2];  // layer output ping
__device__ float g_yb[(size_t)BT * H2];  // layer output pong
__device__ float g_yd[(size_t)BT * H2];  // decoder hidden sequence
__device__ float g_hd[(size_t)B * H2];   // decoder initial hidden (= enc_hidden)

__device__ __forceinline__ float sigmoidf_(float x) {
    return 1.0f / (1.0f + __expf(-x));
}

// ---------------- generic tiled fp32 GEMM:  C[m, n] = A[m,:]·W[n,:] + bias[n]
// A: [M,K] row-major, W: [N,K] row-major (i.e. computes A @ W^T), C uses ldc.
__global__ __launch_bounds__(256) void gemm_bias(
    const float* __restrict__ A, const float* __restrict__ W,
    const float* __restrict__ bias, float* __restrict__ C,
    int M, int N, int K, int ldc)
{
    __shared__ float As[8][128];
    __shared__ float Ws[8][128];
    const int tid = threadIdx.x;
    const int m0 = blockIdx.y * 128, n0 = blockIdx.x * 128;
    const int tx = tid & 15, ty = tid >> 4;

    float acc[8][8];
#pragma unroll
    for (int i = 0; i < 8; i++)
#pragma unroll
        for (int j = 0; j < 8; j++) acc[i][j] = 0.0f;

    for (int k0 = 0; k0 < K; k0 += 8) {
#pragma unroll
        for (int i = 0; i < 4; i++) {
            int idx = tid + i * 256;
            int m = idx >> 3, kk = idx & 7;
            int gm = m0 + m, gk = k0 + kk;
            As[kk][m] = (gm < M && gk < K) ? A[(size_t)gm * K + gk] : 0.0f;
        }
#pragma unroll
        for (int i = 0; i < 4; i++) {
            int idx = tid + i * 256;
            int n = idx >> 3, kk = idx & 7;
            int gn = n0 + n, gk = k0 + kk;
            Ws[kk][n] = (gn < N && gk < K) ? W[(size_t)gn * K + gk] : 0.0f;
        }
        __syncthreads();
#pragma unroll
        for (int k = 0; k < 8; k++) {
            float4 a0 = *(const float4*)&As[k][ty * 8];
            float4 a1 = *(const float4*)&As[k][ty * 8 + 4];
            float4 w0 = *(const float4*)&Ws[k][tx * 8];
            float4 w1 = *(const float4*)&Ws[k][tx * 8 + 4];
            float av[8] = {a0.x, a0.y, a0.z, a0.w, a1.x, a1.y, a1.z, a1.w};
            float wv[8] = {w0.x, w0.y, w0.z, w0.w, w1.x, w1.y, w1.z, w1.w};
#pragma unroll
            for (int i = 0; i < 8; i++)
#pragma unroll
                for (int j = 0; j < 8; j++) acc[i][j] += av[i] * wv[j];
        }
        __syncthreads();
    }
#pragma unroll
    for (int i = 0; i < 8; i++) {
        int gm = m0 + ty * 8 + i;
        if (gm >= M) continue;
#pragma unroll
        for (int j = 0; j < 8; j++) {
            int gn = n0 + tx * 8 + j;
            if (gn < N) C[(size_t)gm * ldc + gn] = acc[i][j] + bias[gn];
        }
    }
}

// ---------------- encoder GRU step (one timestep, both directions) ----------------
// Whh: [2][3H][H] (dir-major), bhh = bhh_base + dir*bhh_stride ([3H] each)
// y:   [B,T,2H]; y also serves as the hidden-state chain (h_t == y[:,t,dir*H:...]).
// xg (global g_xg): [B*T, 6H], dir dir at column offset dir*3H, includes bih.
__global__ __launch_bounds__(256) void enc_step_kernel(
    const float* __restrict__ Whh,
    const float* __restrict__ bhh_base, int bhh_stride,
    float* __restrict__ y, int t)
{
    const int dir = blockIdx.y;
    const int j0  = blockIdx.x * 16;
    const float* Wd  = Whh + (size_t)dir * (G3 * H);
    const float* bhh = bhh_base + dir * bhh_stride;

    __shared__ float hs[64][32];
    __shared__ float ws[48][36];   // +4 pad: kill LDS bank conflicts
    __shared__ float gh[64][48];

    const int tid = threadIdx.x;
    const int tx = tid & 15, ty = tid >> 4;
    float acc[4][3] = {};

    for (int k0 = 0; k0 < H; k0 += 32) {
#pragma unroll
        for (int i = 0; i < 8; i++) {
            int idx = tid + i * 256;
            int r = idx >> 5, c = idx & 31;
            hs[r][c] = (t == 0) ? 0.0f
                     : y[((size_t)(r * T + t - 1)) * H2 + dir * H + k0 + c];
        }
#pragma unroll
        for (int i = 0; i < 6; i++) {
            int idx = tid + i * 256;
            int r = idx >> 5, c = idx & 31;
            int gate = r >> 4, cc = r & 15;
            ws[r][c] = Wd[(size_t)(gate * H + j0 + cc) * H + k0 + c];
        }
        __syncthreads();
#pragma unroll
        for (int k4 = 0; k4 < 8; k4++) {
            float4 b0 = *(const float4*)&ws[tx * 3 + 0][k4 * 4];
            float4 b1 = *(const float4*)&ws[tx * 3 + 1][k4 * 4];
            float4 b2 = *(const float4*)&ws[tx * 3 + 2][k4 * 4];
#pragma unroll
            for (int i = 0; i < 4; i++) {
                float4 a = *(const float4*)&hs[ty * 4 + i][k4 * 4];
                acc[i][0] += a.x * b0.x + a.y * b0.y + a.z * b0.z + a.w * b0.w;
                acc[i][1] += a.x * b1.x + a.y * b1.y + a.z * b1.z + a.w * b1.w;
                acc[i][2] += a.x * b2.x + a.y * b2.y + a.z * b2.z + a.w * b2.w;
            }
        }
        __syncthreads();
    }
#pragma unroll
    for (int i = 0; i < 4; i++)
#pragma unroll
        for (int j = 0; j < 3; j++) gh[ty * 4 + i][tx * 3 + j] = acc[i][j];
    __syncthreads();

#pragma unroll
    for (int i = 0; i < 4; i++) {
        int idx = tid + i * 256;
        int b = idx >> 4, jj = idx & 15;
        int j = j0 + jj;
        const float* xgp = g_xg + (size_t)(b * T + t) * G6 + dir * G3;
        float hr = gh[b][jj]       + bhh[j];
        float hz = gh[b][16 + jj]  + bhh[H + j];
        float hn = gh[b][32 + jj]  + bhh[2 * H + j];
        float r  = sigmoidf_(xgp[j] + hr);
        float z  = sigmoidf_(xgp[H + j] + hz);
        float n  = tanhf(xgp[2 * H + j] + r * hn);
        float hp = (t == 0) ? 0.0f
                 : y[((size_t)(b * T + t - 1)) * H2 + dir * H + j];
        y[((size_t)(b * T + t)) * H2 + dir * H + j] = (1.0f - z) * n + z * hp;
    }
}

// ---------------- decoder GRU step ----------------
// Input gates are constant (zero input): gi = bih = dec_b[0].
// Whh: [3*H2][H2]. h chain lives in g_yd; t==0 hidden comes from g_hd.
__global__ __launch_bounds__(256) void dec_step_kernel(
    const float* __restrict__ Whh,
    const float* __restrict__ bih,
    const float* __restrict__ bhh,
    int t)
{
    const int j0 = blockIdx.x * 16;
    __shared__ float hs[64][32];
    __shared__ float ws[48][36];
    __shared__ float gh[64][48];
    const int tid = threadIdx.x;
    const int tx = tid & 15, ty = tid >> 4;
    float acc[4][3] = {};

    for (int k0 = 0; k0 < H2; k0 += 32) {
#pragma unroll
        for (int i = 0; i < 8; i++) {
            int idx = tid + i * 256;
            int r = idx >> 5, c = idx & 31;
            hs[r][c] = (t == 0) ? g_hd[(size_t)r * H2 + k0 + c]
                                : g_yd[((size_t)(r * T + t - 1)) * H2 + k0 + c];
        }
#pragma unroll
        for (int i = 0; i < 6; i++) {
            int idx = tid + i * 256;
            int r = idx >> 5, c = idx & 31;
            int gate = r >> 4, cc = r & 15;
            ws[r][c] = Whh[(size_t)(gate * H2 + j0 + cc) * H2 + k0 + c];
        }
        __syncthreads();
#pragma unroll
        for (int k4 = 0; k4 < 8; k4++) {
            float4 b0 = *(const float4*)&ws[tx * 3 + 0][k4 * 4];
            float4 b1 = *(const float4*)&ws[tx * 3 + 1][k4 * 4];
            float4 b2 = *(const float4*)&ws[tx * 3 + 2][k4 * 4];
#pragma unroll
            for (int i = 0; i < 4; i++) {
                float4 a = *(const float4*)&hs[ty * 4 + i][k4 * 4];
                acc[i][0] += a.x * b0.x + a.y * b0.y + a.z * b0.z + a.w * b0.w;
                acc[i][1] += a.x * b1.x + a.y * b1.y + a.z * b1.z + a.w * b1.w;
                acc[i][2] += a.x * b2.x + a.y * b2.y + a.z * b2.z + a.w * b2.w;
            }
        }
        __syncthreads();
    }
#pragma unroll
    for (int i = 0; i < 4; i++)
#pragma unroll
        for (int j = 0; j < 3; j++) gh[ty * 4 + i][tx * 3 + j] = acc[i][j];
    __syncthreads();

#pragma unroll
    for (int i = 0; i < 4; i++) {
        int idx = tid + i * 256;
        int b = idx >> 4, jj = idx & 15;
        int j = j0 + jj;
        float hr = gh[b][jj]      + bhh[j];
        float hz = gh[b][16 + jj] + bhh[H2 + j];
        float hn = gh[b][32 + jj] + bhh[2 * H2 + j];
        float r  = sigmoidf_(bih[j] + hr);
        float z  = sigmoidf_(bih[H2 + j] + hz);
        float n  = tanhf(bih[2 * H2 + j] + r * hn);
        float hp = (t == 0) ? g_hd[(size_t)b * H2 + j]
                            : g_yd[((size_t)(b * T + t - 1)) * H2 + j];
        g_yd[((size_t)(b * T + t)) * H2 + j] = (1.0f - z) * n + z * hp;
    }
}

// ---------------- gather enc_hidden (last valid step per sample) ----------------
__global__ void gather_kernel(const float* __restrict__ y,
                              const int* __restrict__ seq_len,
                              float* __restrict__ out_hid)
{
    int idx = blockIdx.x * 256 + threadIdx.x;   // B*H2 = 131072
    int b = idx >> 11, k = idx & (H2 - 1);
    int sl = seq_len[b];
    sl = sl < 1 ? 1 : (sl > T ? T : sl);
    float v = y[((size_t)(b * T + sl - 1)) * H2 + k];
    out_hid[idx] = v;
    g_hd[idx] = v;
}

// ---------------- host launcher ----------------
extern "C" void kernel_launch(void* const* d_in, const int* in_sizes, int n_in,
                              void* d_out, int out_size)
{
    const float* x     = (const float*)d_in[0];   // [B,T,D]
    const int*   slen  = (const int*)  d_in[1];   // [B]
    const float* Wih0  = (const float*)d_in[2];   // [2,3H,D]
    const float* Whh0  = (const float*)d_in[3];   // [2,3H,H]
    const float* b0    = (const float*)d_in[4];   // [2,2,3H]
    const float* Wih   = (const float*)d_in[5];   // [2,2,3H,2H]
    const float* Whh   = (const float*)d_in[6];   // [2,2,3H,H]
    const float* bb    = (const float*)d_in[7];   // [2,2,2,3H]
    // d_in[8] = dec_Wih : unused (decoder input is zeros)
    const float* dWhh  = (const float*)d_in[9];   // [6H,2H]
    const float* db    = (const float*)d_in[10];  // [2,6H]
    const float* oW    = (const float*)d_in[11];  // [D,2H]
    const float* ob    = (const float*)d_in[12];  // [D]
    float* out = (float*)d_out;                   // [B*2H] enc_hidden, then [B,T,D] dec_out

    float *p_xg, *p_ya, *p_yb, *p_yd;
    cudaGetSymbolAddress((void**)&p_xg, g_xg);
    cudaGetSymbolAddress((void**)&p_ya, g_ya);
    cudaGetSymbolAddress((void**)&p_yb, g_yb);
    cudaGetSymbolAddress((void**)&p_yd, g_yd);

    const dim3 gGemm((G3 + 127) / 128, (BT + 127) / 128);   // input-gate GEMMs
    const dim3 gStep(H / 16, 2);                             // encoder step
    const int  nDecBlk = H2 / 16;                            // decoder step

    // ---- encoder layer 0 (K = D = 75) ----
    gemm_bias<<<gGemm, 256>>>(x, Wih0,                 b0,            p_xg,      BT, G3, D, G6);
    gemm_bias<<<gGemm, 256>>>(x, Wih0 + (size_t)G3*D,  b0 + 2*G3,     p_xg + G3, BT, G3, D, G6);
    for (int t = 0; t < T; t++)
        enc_step_kernel<<<gStep, 256>>>(Whh0, b0 + G3, 2 * G3, p_ya, t);

    // ---- encoder layer 1 (l = 0 of extra layers) ----
    gemm_bias<<<gGemm, 256>>>(p_ya, Wih,                      bb,          p_xg,      BT, G3, H2, G6);
    gemm_bias<<<gGemm, 256>>>(p_ya, Wih + (size_t)G3*H2,      bb + 2*G3,   p_xg + G3, BT, G3, H2, G6);
    for (int t = 0; t < T; t++)
        enc_step_kernel<<<gStep, 256>>>(Whh, bb + G3, 2 * G3, p_yb, t);

    // ---- encoder layer 2 (l = 1) ----
    gemm_bias<<<gGemm, 256>>>(p_yb, Wih + (size_t)2*G3*H2,    bb + 4*G3,   p_xg,      BT, G3, H2, G6);
    gemm_bias<<<gGemm, 256>>>(p_yb, Wih + (size_t)3*G3*H2,    bb + 6*G3,   p_xg + G3, BT, G3, H2, G6);
    for (int t = 0; t < T; t++)
        enc_step_kernel<<<gStep, 256>>>(Whh + (size_t)2*G3*H, bb + 5*G3, 2 * G3, p_ya, t);

    // ---- enc_hidden gather (also seeds decoder h0) ----
    gather_kernel<<<(B * H2) / 256, 256>>>(p_ya, slen, out);

    // ---- decoder scan (input gates = db[0], constant) ----
    for (int t = 0; t < T; t++)
        dec_step_kernel<<<nDecBlk, 256>>>(dWhh, db, db + G6, t);

    // ---- output projection: dec_out = ys @ out_W^T + out_b ----
    gemm_bias<<<dim3(1, (BT + 127) / 128), 256>>>(p_yd, oW, ob, out + (size_t)B * H2,
                                                  BT, D, H2, D);
}

// round 3
// speedup vs baseline: 1.8353x; 1.8353x over previous
#include <cuda_runtime.h>
#include <cuda_fp16.h>
#include <math.h>

// Problem dims
#define B   64
#define T   100
#define D   75
#define H   1024
#define H2  2048
#define G3  3072
#define G6  6144
#define BT  6400   // B*T

#define LO_SCALE 4096.0f
#define LO_INV   (1.0f/4096.0f)

// ---------------- scratch (device globals; no allocation) ----------------
__device__ float g_xg[(size_t)BT * G6];  // precomputed input gates (both dirs)
__device__ float g_ya[(size_t)BT * H2];  // layer output ping
__device__ float g_yb[(size_t)BT * H2];  // layer output pong
__device__ float g_yd[(size_t)BT * H2];  // decoder hidden sequence
__device__ float g_hd[(size_t)B * H2];   // decoder initial hidden (= enc_hidden)

__device__ __forceinline__ float sigmoidf_(float x) {
    return 1.0f / (1.0f + __expf(-x));
}

// split fp32 -> (hi fp16, lo fp16 scaled by 2^12)
__device__ __forceinline__ void split2h(float a, __half& hi, __half& lo) {
    hi = __float2half_rn(a);
    lo = __float2half_rn((a - __half2float(hi)) * LO_SCALE);
}

// mma.sync m16n8k16 f16 -> f32 accum
__device__ __forceinline__ void mma16816(float* c, const unsigned* a, const unsigned* b) {
    asm volatile(
        "mma.sync.aligned.m16n8k16.row.col.f32.f16.f16.f32 "
        "{%0,%1,%2,%3},{%4,%5,%6,%7},{%8,%9},{%0,%1,%2,%3};\n"
        : "+f"(c[0]), "+f"(c[1]), "+f"(c[2]), "+f"(c[3])
        : "r"(a[0]), "r"(a[1]), "r"(a[2]), "r"(a[3]), "r"(b[0]), "r"(b[1]));
}

// ================= split-fp16 tensor-core GEMM =================
// C[m,n] = A[m,:]·W[n,:] + bias[n];  A:[M,lda-strided K], W:[N,K] row-major.
// Block tile 128x64, 8 warps (4M x 2N), warp tile 32x32. K chunk 32 (2 x k16).
__global__ __launch_bounds__(256, 2) void gemm_h2(
    const float* __restrict__ A, const float* __restrict__ W,
    const float* __restrict__ bias, float* __restrict__ C,
    int M, int N, int K, int lda, int ldc)
{
    __shared__ alignas(16) __half Ah[128][40], Al_[128][40];
    __shared__ alignas(16) __half Bh[64][40],  Bl_[64][40];

    const int tid = threadIdx.x;
    const int w = tid >> 5, lane = tid & 31;
    const int g4 = lane >> 2, t4 = lane & 3;
    const int m0 = blockIdx.y * 128, n0 = blockIdx.x * 64;
    const int wm = (w >> 1) * 32, wn = (w & 1) * 32;

    float chi[2][4][4] = {}, clo[2][4][4] = {};

    const int nch = (K + 31) / 32;
    for (int ch = 0; ch < nch; ch++) {
        const int k0 = ch * 32;
        // stage A tile (128x32)
#pragma unroll
        for (int i = 0; i < 16; i++) {
            int idx = i * 256 + tid;
            int mm = idx >> 5, kk = idx & 31;
            int gm = m0 + mm, gk = k0 + kk;
            float v = (gm < M && gk < K) ? A[(size_t)gm * lda + gk] : 0.0f;
            __half hi, lo; split2h(v, hi, lo);
            Ah[mm][kk] = hi; Al_[mm][kk] = lo;
        }
        // stage B tile (64x32)
#pragma unroll
        for (int i = 0; i < 8; i++) {
            int idx = i * 256 + tid;
            int nn = idx >> 5, kk = idx & 31;
            int gn = n0 + nn, gk = k0 + kk;
            float v = (gn < N && gk < K) ? W[(size_t)gn * K + gk] : 0.0f;
            __half hi, lo; split2h(v, hi, lo);
            Bh[nn][kk] = hi; Bl_[nn][kk] = lo;
        }
        __syncthreads();

#pragma unroll
        for (int kk16 = 0; kk16 < 2; kk16++) {
            const int kb = kk16 * 16 + 2 * t4;
            unsigned ah[2][4], alo[2][4], bh[4][2], blo[4][2];
#pragma unroll
            for (int mt = 0; mt < 2; mt++) {
                int r0 = wm + mt * 16 + g4;
                ah[mt][0]  = *(const unsigned*)&Ah[r0][kb];
                ah[mt][1]  = *(const unsigned*)&Ah[r0 + 8][kb];
                ah[mt][2]  = *(const unsigned*)&Ah[r0][kb + 8];
                ah[mt][3]  = *(const unsigned*)&Ah[r0 + 8][kb + 8];
                alo[mt][0] = *(const unsigned*)&Al_[r0][kb];
                alo[mt][1] = *(const unsigned*)&Al_[r0 + 8][kb];
                alo[mt][2] = *(const unsigned*)&Al_[r0][kb + 8];
                alo[mt][3] = *(const unsigned*)&Al_[r0 + 8][kb + 8];
            }
#pragma unroll
            for (int nt = 0; nt < 4; nt++) {
                int rn = wn + nt * 8 + g4;
                bh[nt][0]  = *(const unsigned*)&Bh[rn][kb];
                bh[nt][1]  = *(const unsigned*)&Bh[rn][kb + 8];
                blo[nt][0] = *(const unsigned*)&Bl_[rn][kb];
                blo[nt][1] = *(const unsigned*)&Bl_[rn][kb + 8];
            }
#pragma unroll
            for (int mt = 0; mt < 2; mt++)
#pragma unroll
                for (int nt = 0; nt < 4; nt++) {
                    mma16816(chi[mt][nt], ah[mt], bh[nt]);
                    mma16816(clo[mt][nt], ah[mt], blo[nt]);
                    mma16816(clo[mt][nt], alo[mt], bh[nt]);
                }
        }
        __syncthreads();
    }

    // epilogue
#pragma unroll
    for (int mt = 0; mt < 2; mt++)
#pragma unroll
        for (int nt = 0; nt < 4; nt++) {
            int rm = m0 + wm + mt * 16 + g4;
            int cn = n0 + wn + nt * 8 + 2 * t4;
            const float* ch_ = chi[mt][nt];
            const float* cl_ = clo[mt][nt];
            if (rm < M) {
                if (cn < N)     C[(size_t)rm * ldc + cn]     = ch_[0] + cl_[0] * LO_INV + bias[cn];
                if (cn + 1 < N) C[(size_t)rm * ldc + cn + 1] = ch_[1] + cl_[1] * LO_INV + bias[cn + 1];
            }
            if (rm + 8 < M) {
                if (cn < N)     C[(size_t)(rm + 8) * ldc + cn]     = ch_[2] + cl_[2] * LO_INV + bias[cn];
                if (cn + 1 < N) C[(size_t)(rm + 8) * ldc + cn + 1] = ch_[3] + cl_[3] * LO_INV + bias[cn + 1];
            }
        }
}

// ================= encoder GRU step (MMA, fused 3-gate epilogue) =================
// Block: 8 j-columns x 3 gates, M=64 full. 6 warps = (gate, m-half).
// Grid: (H/8, 2 dirs). K = H, chunks of 32, register-prefetch pipeline.
__global__ __launch_bounds__(192) void enc_step_h2(
    const float* __restrict__ Whh,
    const float* __restrict__ bhh_base, int bhh_stride,
    float* __restrict__ y, int t)
{
    const int dir = blockIdx.y;
    const int j0  = blockIdx.x * 8;
    const float* Wd  = Whh + (size_t)dir * ((size_t)G3 * H);
    const float* bhh = bhh_base + (size_t)dir * bhh_stride;

    __shared__ alignas(16) __half Hh[64][40], Hl[64][40];
    __shared__ alignas(16) __half Wh_[24][40], Wl_[24][40];
    __shared__ float gh[3][64][8];

    const int tid = threadIdx.x;
    const int w = tid >> 5, lane = tid & 31;
    const int g = w >> 1, mh = (w & 1) * 32;
    const int g4 = lane >> 2, t4 = lane & 3;

    float chi[2][4] = {}, clo[2][4] = {};

    if (t > 0) {
        float ph[11], pw[4];
        // preload chunk 0
#pragma unroll
        for (int i = 0; i < 11; i++) {
            int idx = i * 192 + tid;
            ph[i] = (idx < 2048)
                  ? y[((size_t)((idx >> 5) * T + t - 1)) * H2 + dir * H + (idx & 31)]
                  : 0.0f;
        }
#pragma unroll
        for (int i = 0; i < 4; i++) {
            int idx = i * 192 + tid;
            int rr = idx >> 5, kk = idx & 31;
            int gg = rr >> 3, jj = rr & 7;
            pw[i] = Wd[(size_t)(gg * H + j0 + jj) * H + kk];
        }

        for (int ch = 0; ch < 32; ch++) {
            // store current chunk to smem (split)
#pragma unroll
            for (int i = 0; i < 11; i++) {
                int idx = i * 192 + tid;
                if (idx < 2048) {
                    int mm = idx >> 5, kk = idx & 31;
                    __half hi, lo; split2h(ph[i], hi, lo);
                    Hh[mm][kk] = hi; Hl[mm][kk] = lo;
                }
            }
#pragma unroll
            for (int i = 0; i < 4; i++) {
                int idx = i * 192 + tid;
                int rr = idx >> 5, kk = idx & 31;
                __half hi, lo; split2h(pw[i], hi, lo);
                Wh_[rr][kk] = hi; Wl_[rr][kk] = lo;
            }
            __syncthreads();

            // prefetch next chunk
            if (ch < 31) {
                int k0n = (ch + 1) * 32;
#pragma unroll
                for (int i = 0; i < 11; i++) {
                    int idx = i * 192 + tid;
                    ph[i] = (idx < 2048)
                          ? y[((size_t)((idx >> 5) * T + t - 1)) * H2 + dir * H + k0n + (idx & 31)]
                          : 0.0f;
                }
#pragma unroll
                for (int i = 0; i < 4; i++) {
                    int idx = i * 192 + tid;
                    int rr = idx >> 5, kk = idx & 31;
                    int gg = rr >> 3, jj = rr & 7;
                    pw[i] = Wd[(size_t)(gg * H + j0 + jj) * H + k0n + kk];
                }
            }

            // MMA: 2 x k16 per chunk
#pragma unroll
            for (int kk16 = 0; kk16 < 2; kk16++) {
                const int kb = kk16 * 16 + 2 * t4;
                unsigned ah[2][4], alo[2][4], bh[2], blo[2];
#pragma unroll
                for (int mt = 0; mt < 2; mt++) {
                    int r0 = mh + mt * 16 + g4;
                    ah[mt][0]  = *(const unsigned*)&Hh[r0][kb];
                    ah[mt][1]  = *(const unsigned*)&Hh[r0 + 8][kb];
                    ah[mt][2]  = *(const unsigned*)&Hh[r0][kb + 8];
                    ah[mt][3]  = *(const unsigned*)&Hh[r0 + 8][kb + 8];
                    alo[mt][0] = *(const unsigned*)&Hl[r0][kb];
                    alo[mt][1] = *(const unsigned*)&Hl[r0 + 8][kb];
                    alo[mt][2] = *(const unsigned*)&Hl[r0][kb + 8];
                    alo[mt][3] = *(const unsigned*)&Hl[r0 + 8][kb + 8];
                }
                int rn = g * 8 + g4;
                bh[0]  = *(const unsigned*)&Wh_[rn][kb];
                bh[1]  = *(const unsigned*)&Wh_[rn][kb + 8];
                blo[0] = *(const unsigned*)&Wl_[rn][kb];
                blo[1] = *(const unsigned*)&Wl_[rn][kb + 8];
#pragma unroll
                for (int mt = 0; mt < 2; mt++) {
                    mma16816(chi[mt], ah[mt], bh);
                    mma16816(clo[mt], ah[mt], blo);
                    mma16816(clo[mt], alo[mt], bh);
                }
            }
            __syncthreads();
        }
    }

    // write gh (per-warp disjoint)
#pragma unroll
    for (int mt = 0; mt < 2; mt++) {
        int rm = mh + mt * 16 + g4;
        int cn = 2 * t4;
        gh[g][rm][cn]         = chi[mt][0] + clo[mt][0] * LO_INV;
        gh[g][rm][cn + 1]     = chi[mt][1] + clo[mt][1] * LO_INV;
        gh[g][rm + 8][cn]     = chi[mt][2] + clo[mt][2] * LO_INV;
        gh[g][rm + 8][cn + 1] = chi[mt][3] + clo[mt][3] * LO_INV;
    }
    __syncthreads();

    // fused gate epilogue: 64 m x 8 j outputs
    for (int o = tid; o < 512; o += 192) {
        int mm = o >> 3, jj = o & 7;
        int j = j0 + jj;
        const float* xgp = g_xg + (size_t)(mm * T + t) * G6 + dir * G3;
        float hr = gh[0][mm][jj] + bhh[j];
        float hz = gh[1][mm][jj] + bhh[H + j];
        float hn = gh[2][mm][jj] + bhh[2 * H + j];
        float r  = sigmoidf_(xgp[j] + hr);
        float z  = sigmoidf_(xgp[H + j] + hz);
        float n  = tanhf(xgp[2 * H + j] + r * hn);
        float hp = (t == 0) ? 0.0f
                 : y[((size_t)(mm * T + t - 1)) * H2 + dir * H + j];
        y[((size_t)(mm * T + t)) * H2 + dir * H + j] = (1.0f - z) * n + z * hp;
    }
}

// ================= decoder GRU step (MMA) =================
// Hidden 2048, gates 3x2048. Block = 8 j x 3 gates, grid H2/8 = 256. K = H2.
__global__ __launch_bounds__(192) void dec_step_h2(
    const float* __restrict__ Whh,
    const float* __restrict__ bih,
    const float* __restrict__ bhh,
    int t)
{
    const int j0 = blockIdx.x * 8;

    __shared__ alignas(16) __half Hh[64][40], Hl[64][40];
    __shared__ alignas(16) __half Wh_[24][40], Wl_[24][40];
    __shared__ float gh[3][64][8];

    const int tid = threadIdx.x;
    const int w = tid >> 5, lane = tid & 31;
    const int g = w >> 1, mh = (w & 1) * 32;
    const int g4 = lane >> 2, t4 = lane & 3;

    float chi[2][4] = {}, clo[2][4] = {};

    float ph[11], pw[4];
    // preload chunk 0
#pragma unroll
    for (int i = 0; i < 11; i++) {
        int idx = i * 192 + tid;
        float v = 0.0f;
        if (idx < 2048) {
            int mm = idx >> 5, kk = idx & 31;
            v = (t == 0) ? g_hd[(size_t)mm * H2 + kk]
                         : g_yd[((size_t)(mm * T + t - 1)) * H2 + kk];
        }
        ph[i] = v;
    }
#pragma unroll
    for (int i = 0; i < 4; i++) {
        int idx = i * 192 + tid;
        int rr = idx >> 5, kk = idx & 31;
        int gg = rr >> 3, jj = rr & 7;
        pw[i] = Whh[(size_t)(gg * H2 + j0 + jj) * H2 + kk];
    }

    for (int ch = 0; ch < 64; ch++) {
#pragma unroll
        for (int i = 0; i < 11; i++) {
            int idx = i * 192 + tid;
            if (idx < 2048) {
                int mm = idx >> 5, kk = idx & 31;
                __half hi, lo; split2h(ph[i], hi, lo);
                Hh[mm][kk] = hi; Hl[mm][kk] = lo;
            }
        }
#pragma unroll
        for (int i = 0; i < 4; i++) {
            int idx = i * 192 + tid;
            int rr = idx >> 5, kk = idx & 31;
            __half hi, lo; split2h(pw[i], hi, lo);
            Wh_[rr][kk] = hi; Wl_[rr][kk] = lo;
        }
        __syncthreads();

        if (ch < 63) {
            int k0n = (ch + 1) * 32;
#pragma unroll
            for (int i = 0; i < 11; i++) {
                int idx = i * 192 + tid;
                float v = 0.0f;
                if (idx < 2048) {
                    int mm = idx >> 5, kk = idx & 31;
                    v = (t == 0) ? g_hd[(size_t)mm * H2 + k0n + kk]
                                 : g_yd[((size_t)(mm * T + t - 1)) * H2 + k0n + kk];
                }
                ph[i] = v;
            }
#pragma unroll
            for (int i = 0; i < 4; i++) {
                int idx = i * 192 + tid;
                int rr = idx >> 5, kk = idx & 31;
                int gg = rr >> 3, jj = rr & 7;
                pw[i] = Whh[(size_t)(gg * H2 + j0 + jj) * H2 + k0n + kk];
            }
        }

#pragma unroll
        for (int kk16 = 0; kk16 < 2; kk16++) {
            const int kb = kk16 * 16 + 2 * t4;
            unsigned ah[2][4], alo[2][4], bh[2], blo[2];
#pragma unroll
            for (int mt = 0; mt < 2; mt++) {
                int r0 = mh + mt * 16 + g4;
                ah[mt][0]  = *(const unsigned*)&Hh[r0][kb];
                ah[mt][1]  = *(const unsigned*)&Hh[r0 + 8][kb];
                ah[mt][2]  = *(const unsigned*)&Hh[r0][kb + 8];
                ah[mt][3]  = *(const unsigned*)&Hh[r0 + 8][kb + 8];
                alo[mt][0] = *(const unsigned*)&Hl[r0][kb];
                alo[mt][1] = *(const unsigned*)&Hl[r0 + 8][kb];
                alo[mt][2] = *(const unsigned*)&Hl[r0][kb + 8];
                alo[mt][3] = *(const unsigned*)&Hl[r0 + 8][kb + 8];
            }
            int rn = g * 8 + g4;
            bh[0]  = *(const unsigned*)&Wh_[rn][kb];
            bh[1]  = *(const unsigned*)&Wh_[rn][kb + 8];
            blo[0] = *(const unsigned*)&Wl_[rn][kb];
            blo[1] = *(const unsigned*)&Wl_[rn][kb + 8];
#pragma unroll
            for (int mt = 0; mt < 2; mt++) {
                mma16816(chi[mt], ah[mt], bh);
                mma16816(clo[mt], ah[mt], blo);
                mma16816(clo[mt], alo[mt], bh);
            }
        }
        __syncthreads();
    }

#pragma unroll
    for (int mt = 0; mt < 2; mt++) {
        int rm = mh + mt * 16 + g4;
        int cn = 2 * t4;
        gh[g][rm][cn]         = chi[mt][0] + clo[mt][0] * LO_INV;
        gh[g][rm][cn + 1]     = chi[mt][1] + clo[mt][1] * LO_INV;
        gh[g][rm + 8][cn]     = chi[mt][2] + clo[mt][2] * LO_INV;
        gh[g][rm + 8][cn + 1] = chi[mt][3] + clo[mt][3] * LO_INV;
    }
    __syncthreads();

    for (int o = tid; o < 512; o += 192) {
        int mm = o >> 3, jj = o & 7;
        int j = j0 + jj;
        float hr = gh[0][mm][jj] + bhh[j];
        float hz = gh[1][mm][jj] + bhh[H2 + j];
        float hn = gh[2][mm][jj] + bhh[2 * H2 + j];
        float r  = sigmoidf_(bih[j] + hr);
        float z  = sigmoidf_(bih[H2 + j] + hz);
        float n  = tanhf(bih[2 * H2 + j] + r * hn);
        float hp = (t == 0) ? g_hd[(size_t)mm * H2 + j]
                            : g_yd[((size_t)(mm * T + t - 1)) * H2 + j];
        g_yd[((size_t)(mm * T + t)) * H2 + j] = (1.0f - z) * n + z * hp;
    }
}

// ---------------- gather enc_hidden (last valid step per sample) ----------------
__global__ void gather_kernel(const float* __restrict__ y,
                              const int* __restrict__ seq_len,
                              float* __restrict__ out_hid)
{
    int idx = blockIdx.x * 256 + threadIdx.x;   // B*H2 = 131072
    int b = idx >> 11, k = idx & (H2 - 1);
    int sl = seq_len[b];
    sl = sl < 1 ? 1 : (sl > T ? T : sl);
    float v = y[((size_t)(b * T + sl - 1)) * H2 + k];
    out_hid[idx] = v;
    g_hd[idx] = v;
}

// ---------------- host launcher ----------------
extern "C" void kernel_launch(void* const* d_in, const int* in_sizes, int n_in,
                              void* d_out, int out_size)
{
    const float* x     = (const float*)d_in[0];   // [B,T,D]
    const int*   slen  = (const int*)  d_in[1];   // [B]
    const float* Wih0  = (const float*)d_in[2];   // [2,3H,D]
    const float* Whh0  = (const float*)d_in[3];   // [2,3H,H]
    const float* b0    = (const float*)d_in[4];   // [2,2,3H]
    const float* Wih   = (const float*)d_in[5];   // [2,2,3H,2H]
    const float* Whh   = (const float*)d_in[6];   // [2,2,3H,H]
    const float* bb    = (const float*)d_in[7];   // [2,2,2,3H]
    // d_in[8] = dec_Wih : unused (decoder input is zeros)
    const float* dWhh  = (const float*)d_in[9];   // [6H,2H]
    const float* db    = (const float*)d_in[10];  // [2,6H]
    const float* oW    = (const float*)d_in[11];  // [D,2H]
    const float* ob    = (const float*)d_in[12];  // [D]
    float* out = (float*)d_out;                   // [B*2H] enc_hidden, then [B,T,D] dec_out

    float *p_xg, *p_ya, *p_yb, *p_yd;
    cudaGetSymbolAddress((void**)&p_xg, g_xg);
    cudaGetSymbolAddress((void**)&p_ya, g_ya);
    cudaGetSymbolAddress((void**)&p_yb, g_yb);
    cudaGetSymbolAddress((void**)&p_yd, g_yd);

    const dim3 gG(G3 / 64, BT / 128);      // big input-gate GEMMs: 48 x 50
    const dim3 gE(H / 8, 2);               // encoder step: 128 x 2
    const int  gDc = H2 / 8;               // decoder step: 256

    // ---- encoder layer 0 (K = D = 75) ----
    gemm_h2<<<gG, 256>>>(x, Wih0,                     b0,          p_xg,      BT, G3, D, D, G6);
    gemm_h2<<<gG, 256>>>(x, Wih0 + (size_t)G3 * D,    b0 + 2*G3,   p_xg + G3, BT, G3, D, D, G6);
    for (int t = 0; t < T; t++)
        enc_step_h2<<<gE, 192>>>(Whh0, b0 + G3, 2 * G3, p_ya, t);

    // ---- encoder layer 1 ----
    gemm_h2<<<gG, 256>>>(p_ya, Wih,                   bb,          p_xg,      BT, G3, H2, H2, G6);
    gemm_h2<<<gG, 256>>>(p_ya, Wih + (size_t)G3*H2,   bb + 2*G3,   p_xg + G3, BT, G3, H2, H2, G6);
    for (int t = 0; t < T; t++)
        enc_step_h2<<<gE, 192>>>(Whh, bb + G3, 2 * G3, p_yb, t);

    // ---- encoder layer 2 ----
    gemm_h2<<<gG, 256>>>(p_yb, Wih + (size_t)2*G3*H2, bb + 4*G3,   p_xg,      BT, G3, H2, H2, G6);
    gemm_h2<<<gG, 256>>>(p_yb, Wih + (size_t)3*G3*H2, bb + 6*G3,   p_xg + G3, BT, G3, H2, H2, G6);
    for (int t = 0; t < T; t++)
        enc_step_h2<<<gE, 192>>>(Whh + (size_t)2*G3*H, bb + 5*G3, 2 * G3, p_ya, t);

    // ---- enc_hidden gather (also seeds decoder h0) ----
    gather_kernel<<<(B * H2) / 256, 256>>>(p_ya, slen, out);

    // ---- decoder scan (input gates = db[0], constant) ----
    for (int t = 0; t < T; t++)
        dec_step_h2<<<gDc, 192>>>(dWhh, db, db + G6, t);

    // ---- output projection: dec_out = ys @ out_W^T + out_b ----
    gemm_h2<<<dim3(2, BT / 128), 256>>>(p_yd, oW, ob, out + (size_t)B * H2,
                                        BT, D, H2, H2, D);
}

// round 6
// speedup vs baseline: 2.3213x; 1.2648x over previous
#include <cuda_runtime.h>
#include <cuda_fp16.h>
#include <math.h>

// Problem dims
#define B   64
#define T   100
#define D   75
#define DP  80      // padded K for layer-0 / x
#define H   1024
#define H2  2048
#define G3  3072
#define G6  6144
#define BT  6400

#define LO_SCALE 4096.0f
#define LO_INV   (1.0f/4096.0f)

// ---------------- scratch (device globals; no allocation) ----------------
__device__ float   g_xg[(size_t)BT * G6];          // input gates (fp32)
__device__ __half2 g_y2a[(size_t)BT * H2];         // layer output ping (packed hi/lo)
__device__ __half2 g_y2b[(size_t)BT * H2];         // layer output pong
__device__ __half2 g_y2d[(size_t)BT * H2];         // decoder hidden sequence
__device__ __half2 g_x2[(size_t)BT * DP];          // packed padded x
__device__ __half2 g_ehr[(size_t)2 * 2 * B * H];   // enc h ring [buf][dir][B][H]
__device__ __half2 g_dhr[(size_t)2 * B * H2];      // dec h ring [buf][B][H2]
// pre-split weight planes (hi / lo*4096)
__device__ __half s_Whh0h[(size_t)2 * G3 * H],  s_Whh0l[(size_t)2 * G3 * H];
__device__ __half s_Whhh [(size_t)4 * G3 * H],  s_Whhl [(size_t)4 * G3 * H];
__device__ __half s_dWh  [(size_t)G6 * H2],     s_dWl  [(size_t)G6 * H2];
__device__ __half s_Wihh [(size_t)4 * G3 * H2], s_Wihl [(size_t)4 * G3 * H2];
__device__ __half s_Wih0h[(size_t)2 * G3 * DP], s_Wih0l[(size_t)2 * G3 * DP];
__device__ __half s_oWh  [(size_t)D * H2],      s_oWl  [(size_t)D * H2];

__device__ __forceinline__ float sigmoidf_(float x) { return 1.0f / (1.0f + __expf(-x)); }

__device__ __forceinline__ __half2 packsplit(float v) {
    __half hi = __float2half_rn(v);
    __half lo = __float2half_rn((v - __half2float(hi)) * LO_SCALE);
    return __halves2half2(hi, lo);
}
__device__ __forceinline__ float unpackf(__half2 p) {
    return __half2float(__low2half(p)) + __half2float(__high2half(p)) * LO_INV;
}

// 4 packed half2 (hi,lo) -> 4 contiguous hi halves + 4 contiguous lo halves
__device__ __forceinline__ void unpack4(uint4 v, uint2& hi, uint2& lo) {
    __half2 a0 = *(__half2*)&v.x, a1 = *(__half2*)&v.y;
    __half2 a2 = *(__half2*)&v.z, a3 = *(__half2*)&v.w;
    __half2 h01 = __lows2half2(a0, a1),  h23 = __lows2half2(a2, a3);
    __half2 l01 = __highs2half2(a0, a1), l23 = __highs2half2(a2, a3);
    hi = make_uint2(*(unsigned*)&h01, *(unsigned*)&h23);
    lo = make_uint2(*(unsigned*)&l01, *(unsigned*)&l23);
}

__device__ __forceinline__ void mma16816(float* c, const unsigned* a, const unsigned* b) {
    asm volatile(
        "mma.sync.aligned.m16n8k16.row.col.f32.f16.f16.f32 "
        "{%0,%1,%2,%3},{%4,%5,%6,%7},{%8,%9},{%0,%1,%2,%3};\n"
        : "+f"(c[0]), "+f"(c[1]), "+f"(c[2]), "+f"(c[3])
        : "r"(a[0]), "r"(a[1]), "r"(a[2]), "r"(a[3]), "r"(b[0]), "r"(b[1]));
}

// ================= prep kernels =================
__global__ void k_split(const float* __restrict__ src, __half* __restrict__ hi,
                        __half* __restrict__ lo, int n) {
    for (int i = blockIdx.x * blockDim.x + threadIdx.x; i < n; i += gridDim.x * blockDim.x) {
        float v = src[i];
        __half h = __float2half_rn(v);
        hi[i] = h;
        lo[i] = __float2half_rn((v - __half2float(h)) * LO_SCALE);
    }
}
__global__ void k_split_pad(const float* __restrict__ src, __half* __restrict__ hi,
                            __half* __restrict__ lo, int rows, int kin, int kout) {
    int n = rows * kout;
    for (int i = blockIdx.x * blockDim.x + threadIdx.x; i < n; i += gridDim.x * blockDim.x) {
        int r = i / kout, k = i - r * kout;
        float v = (k < kin) ? src[(size_t)r * kin + k] : 0.0f;
        __half h = __float2half_rn(v);
        hi[i] = h;
        lo[i] = __float2half_rn((v - __half2float(h)) * LO_SCALE);
    }
}
__global__ void k_pack_pad(const float* __restrict__ src, __half2* __restrict__ dst,
                           int rows, int kin, int kout) {
    int n = rows * kout;
    for (int i = blockIdx.x * blockDim.x + threadIdx.x; i < n; i += gridDim.x * blockDim.x) {
        int r = i / kout, k = i - r * kout;
        float v = (k < kin) ? src[(size_t)r * kin + k] : 0.0f;
        dst[i] = packsplit(v);
    }
}

// ================= GEMM: packed-A x pre-split-W, tensor cores =================
// C[m,n] = A[m,:]·W[n,:] + bias[n]. Tile 128x64, 8 warps (4M x 2N).
__global__ __launch_bounds__(256) void gemm_h2p(
    const __half2* __restrict__ A2, int lda,
    const __half* __restrict__ Whi, const __half* __restrict__ Wlo,
    const float* __restrict__ bias, float* __restrict__ C,
    int M, int N, int K, int ldc)
{
    __shared__ __half Ah[128][40], Al[128][40];
    __shared__ __half Bh[64][40],  Bl[64][40];

    const int tid = threadIdx.x;
    const int w = tid >> 5, lane = tid & 31;
    const int g4 = lane >> 2, t4 = lane & 3;
    const int m0 = blockIdx.y * 128, n0 = blockIdx.x * 64;
    const int wm = (w >> 1) * 32, wn = (w & 1) * 32;

    const int amm[4] = {(0*256+tid)>>3, (1*256+tid)>>3, (2*256+tid)>>3, (3*256+tid)>>3};
    const int akq = tid & 7;
    const int wnn = tid >> 2, wkq = tid & 3;

    float chi[2][4][4] = {}, clo[2][4][4] = {};
    const int nch = (K + 31) / 32;

    uint4 pa[4], pwh, pwl;
    const uint4 z4 = make_uint4(0, 0, 0, 0);
    {
        const int k0 = 0;
#pragma unroll
        for (int i = 0; i < 4; i++) {
            int gm = m0 + amm[i];
            pa[i] = (gm < M && k0 + akq * 4 < K)
                  ? *(const uint4*)&A2[(size_t)gm * lda + k0 + akq * 4] : z4;
        }
        int gn = n0 + wnn;
        bool okw = (gn < N) && (k0 + wkq * 8 < K);
        size_t wa = (size_t)gn * K + k0 + wkq * 8;
        pwh = okw ? *(const uint4*)&Whi[wa] : z4;
        pwl = okw ? *(const uint4*)&Wlo[wa] : z4;
    }

    for (int ch = 0; ch < nch; ch++) {
#pragma unroll
        for (int i = 0; i < 4; i++) {
            uint2 hi, lo; unpack4(pa[i], hi, lo);
            *(uint2*)&Ah[amm[i]][akq * 4] = hi;
            *(uint2*)&Al[amm[i]][akq * 4] = lo;
        }
        *(uint4*)&Bh[wnn][wkq * 8] = pwh;
        *(uint4*)&Bl[wnn][wkq * 8] = pwl;
        __syncthreads();

        if (ch + 1 < nch) {
            const int k0 = (ch + 1) * 32;
#pragma unroll
            for (int i = 0; i < 4; i++) {
                int gm = m0 + amm[i];
                pa[i] = (gm < M && k0 + akq * 4 < K)
                      ? *(const uint4*)&A2[(size_t)gm * lda + k0 + akq * 4] : z4;
            }
            int gn = n0 + wnn;
            bool okw = (gn < N) && (k0 + wkq * 8 < K);
            size_t wa = (size_t)gn * K + k0 + wkq * 8;
            pwh = okw ? *(const uint4*)&Whi[wa] : z4;
            pwl = okw ? *(const uint4*)&Wlo[wa] : z4;
        }

#pragma unroll
        for (int kk16 = 0; kk16 < 2; kk16++) {
            const int kb = kk16 * 16 + 2 * t4;
            unsigned ah[2][4], al[2][4], bh[4][2], bl[4][2];
#pragma unroll
            for (int mt = 0; mt < 2; mt++) {
                int r0 = wm + mt * 16 + g4;
                ah[mt][0] = *(const unsigned*)&Ah[r0][kb];
                ah[mt][1] = *(const unsigned*)&Ah[r0 + 8][kb];
                ah[mt][2] = *(const unsigned*)&Ah[r0][kb + 8];
                ah[mt][3] = *(const unsigned*)&Ah[r0 + 8][kb + 8];
                al[mt][0] = *(const unsigned*)&Al[r0][kb];
                al[mt][1] = *(const unsigned*)&Al[r0 + 8][kb];
                al[mt][2] = *(const unsigned*)&Al[r0][kb + 8];
                al[mt][3] = *(const unsigned*)&Al[r0 + 8][kb + 8];
            }
#pragma unroll
            for (int nt = 0; nt < 4; nt++) {
                int rn = wn + nt * 8 + g4;
                bh[nt][0] = *(const unsigned*)&Bh[rn][kb];
                bh[nt][1] = *(const unsigned*)&Bh[rn][kb + 8];
                bl[nt][0] = *(const unsigned*)&Bl[rn][kb];
                bl[nt][1] = *(const unsigned*)&Bl[rn][kb + 8];
            }
#pragma unroll
            for (int mt = 0; mt < 2; mt++)
#pragma unroll
                for (int nt = 0; nt < 4; nt++) {
                    mma16816(chi[mt][nt], ah[mt], bh[nt]);
                    mma16816(clo[mt][nt], ah[mt], bl[nt]);
                    mma16816(clo[mt][nt], al[mt], bh[nt]);
                }
        }
        __syncthreads();
    }

#pragma unroll
    for (int mt = 0; mt < 2; mt++)
#pragma unroll
        for (int nt = 0; nt < 4; nt++) {
            int rm = m0 + wm + mt * 16 + g4;
            int cn = n0 + wn + nt * 8 + 2 * t4;
            const float* ch_ = chi[mt][nt];
            const float* cl_ = clo[mt][nt];
            if (rm < M) {
                if (cn < N)     C[(size_t)rm * ldc + cn]     = ch_[0] + cl_[0] * LO_INV + bias[cn];
                if (cn + 1 < N) C[(size_t)rm * ldc + cn + 1] = ch_[1] + cl_[1] * LO_INV + bias[cn + 1];
            }
            if (rm + 8 < M) {
                if (cn < N)     C[(size_t)(rm + 8) * ldc + cn]     = ch_[2] + cl_[2] * LO_INV + bias[cn];
                if (cn + 1 < N) C[(size_t)(rm + 8) * ldc + cn + 1] = ch_[3] + cl_[3] * LO_INV + bias[cn + 1];
            }
        }
}

// ================= encoder GRU step: 16 j-cols x 3 gates, 12 warps =================
__global__ __launch_bounds__(384) void enc_step_h3(
    const __half* __restrict__ Whi_all, const __half* __restrict__ Wlo_all,
    const float* __restrict__ bhh_base, int bhh_stride,
    __half2* __restrict__ y2, int t)
{
    const int dir = blockIdx.y;
    const int j0  = blockIdx.x * 16;
    const __half* Whi = Whi_all + (size_t)dir * G3 * H;
    const __half* Wlo = Wlo_all + (size_t)dir * G3 * H;
    const float* bhh = bhh_base + (size_t)dir * bhh_stride;
    const __half2* ring_rd = g_ehr + ((size_t)((t & 1) * 2 + dir)) * B * H;
    __half2*       ring_wr = g_ehr + ((size_t)(((t + 1) & 1) * 2 + dir)) * B * H;

    __shared__ __half Hh[64][40], Hl[64][40];
    __shared__ __half Wh_[48][40], Wl_[48][40];
    __shared__ float gh[3][64][16];

    const int tid = threadIdx.x;
    const int w = tid >> 5, lane = tid & 31;
    const int g = w >> 2, mh = ((w >> 1) & 1) * 32, nh = (w & 1) * 8;
    const int g4 = lane >> 2, t4 = lane & 3;

    float chi[2][4] = {}, clo[2][4] = {};

    if (t > 0) {
        const int hrow = tid >> 3, hkq = tid & 7;
        const int idx1 = tid + 384;
        const int hrow1 = idx1 >> 3, hkq1 = idx1 & 7;
        const bool has2 = (tid < 128);
        const bool wishi = (tid < 192);
        const int widx = wishi ? tid : tid - 192;
        const int wrow = widx >> 2, wkq = widx & 3;
        const int wg = wrow >> 4, wjj = wrow & 15;
        const size_t wbase = ((size_t)(wg * H + j0 + wjj)) * H + wkq * 8;
        const __half* wsrc = wishi ? Whi : Wlo;

        uint4 ph0, ph1, pw;
        ph0 = *(const uint4*)&ring_rd[(size_t)hrow * H + hkq * 4];
        if (has2) ph1 = *(const uint4*)&ring_rd[(size_t)hrow1 * H + hkq1 * 4];
        pw = *(const uint4*)&wsrc[wbase];

        for (int ch = 0; ch < H / 32; ch++) {
            {
                uint2 hi, lo; unpack4(ph0, hi, lo);
                *(uint2*)&Hh[hrow][hkq * 4] = hi;
                *(uint2*)&Hl[hrow][hkq * 4] = lo;
                if (has2) {
                    unpack4(ph1, hi, lo);
                    *(uint2*)&Hh[hrow1][hkq1 * 4] = hi;
                    *(uint2*)&Hl[hrow1][hkq1 * 4] = lo;
                }
                if (wishi) *(uint4*)&Wh_[wrow][wkq * 8] = pw;
                else       *(uint4*)&Wl_[wrow][wkq * 8] = pw;
            }
            __syncthreads();

            if (ch + 1 < H / 32) {
                const int k0 = (ch + 1) * 32;
                ph0 = *(const uint4*)&ring_rd[(size_t)hrow * H + k0 + hkq * 4];
                if (has2) ph1 = *(const uint4*)&ring_rd[(size_t)hrow1 * H + k0 + hkq1 * 4];
                pw = *(const uint4*)&wsrc[wbase + k0];
            }

#pragma unroll
            for (int kk16 = 0; kk16 < 2; kk16++) {
                const int kb = kk16 * 16 + 2 * t4;
                unsigned ah[2][4], al[2][4], bh[2], bl[2];
#pragma unroll
                for (int mt = 0; mt < 2; mt++) {
                    int r0 = mh + mt * 16 + g4;
                    ah[mt][0] = *(const unsigned*)&Hh[r0][kb];
                    ah[mt][1] = *(const unsigned*)&Hh[r0 + 8][kb];
                    ah[mt][2] = *(const unsigned*)&Hh[r0][kb + 8];
                    ah[mt][3] = *(const unsigned*)&Hh[r0 + 8][kb + 8];
                    al[mt][0] = *(const unsigned*)&Hl[r0][kb];
                    al[mt][1] = *(const unsigned*)&Hl[r0 + 8][kb];
                    al[mt][2] = *(const unsigned*)&Hl[r0][kb + 8];
                    al[mt][3] = *(const unsigned*)&Hl[r0 + 8][kb + 8];
                }
                int rn = g * 16 + nh + g4;
                bh[0] = *(const unsigned*)&Wh_[rn][kb];
                bh[1] = *(const unsigned*)&Wh_[rn][kb + 8];
                bl[0] = *(const unsigned*)&Wl_[rn][kb];
                bl[1] = *(const unsigned*)&Wl_[rn][kb + 8];
#pragma unroll
                for (int mt = 0; mt < 2; mt++) {
                    mma16816(chi[mt], ah[mt], bh);
                    mma16816(clo[mt], ah[mt], bl);
                    mma16816(clo[mt], al[mt], bh);
                }
            }
            __syncthreads();
        }
    }

#pragma unroll
    for (int mt = 0; mt < 2; mt++) {
        int rm = mh + mt * 16 + g4, cn = nh + 2 * t4;
        gh[g][rm][cn]         = chi[mt][0] + clo[mt][0] * LO_INV;
        gh[g][rm][cn + 1]     = chi[mt][1] + clo[mt][1] * LO_INV;
        gh[g][rm + 8][cn]     = chi[mt][2] + clo[mt][2] * LO_INV;
        gh[g][rm + 8][cn + 1] = chi[mt][3] + clo[mt][3] * LO_INV;
    }
    __syncthreads();

    for (int o = tid; o < 1024; o += 384) {
        int mm = o >> 4, jj = o & 15, j = j0 + jj;
        const float* xgp = g_xg + (size_t)(mm * T + t) * G6 + dir * G3;
        float r = sigmoidf_(xgp[j]         + gh[0][mm][jj] + bhh[j]);
        float z = sigmoidf_(xgp[H + j]     + gh[1][mm][jj] + bhh[H + j]);
        float n = tanhf    (xgp[2 * H + j] + r * (gh[2][mm][jj] + bhh[2 * H + j]));
        float hp = (t == 0) ? 0.0f : unpackf(ring_rd[(size_t)mm * H + j]);
        float hv = (1.0f - z) * n + z * hp;
        __half2 pv = packsplit(hv);
        y2[((size_t)(mm * T + t)) * H2 + dir * H + j] = pv;
        ring_wr[(size_t)mm * H + j] = pv;
    }
}

// ================= decoder GRU step =================
__global__ __launch_bounds__(384) void dec_step_h3(
    const float* __restrict__ bih, const float* __restrict__ bhh, int t)
{
    const int j0 = blockIdx.x * 16;
    const __half2* ring_rd = g_dhr + ((size_t)(t & 1)) * B * H2;
    __half2*       ring_wr = g_dhr + ((size_t)((t + 1) & 1)) * B * H2;

    __shared__ __half Hh[64][40], Hl[64][40];
    __shared__ __half Wh_[48][40], Wl_[48][40];
    __shared__ float gh[3][64][16];

    const int tid = threadIdx.x;
    const int w = tid >> 5, lane = tid & 31;
    const int g = w >> 2, mh = ((w >> 1) & 1) * 32, nh = (w & 1) * 8;
    const int g4 = lane >> 2, t4 = lane & 3;

    float chi[2][4] = {}, clo[2][4] = {};

    {
        const int hrow = tid >> 3, hkq = tid & 7;
        const int idx1 = tid + 384;
        const int hrow1 = idx1 >> 3, hkq1 = idx1 & 7;
        const bool has2 = (tid < 128);
        const bool wishi = (tid < 192);
        const int widx = wishi ? tid : tid - 192;
        const int wrow = widx >> 2, wkq = widx & 3;
        const int wg = wrow >> 4, wjj = wrow & 15;
        const size_t wbase = ((size_t)(wg * H2 + j0 + wjj)) * H2 + wkq * 8;
        const __half* wsrc = wishi ? s_dWh : s_dWl;

        uint4 ph0, ph1, pw;
        ph0 = *(const uint4*)&ring_rd[(size_t)hrow * H2 + hkq * 4];
        if (has2) ph1 = *(const uint4*)&ring_rd[(size_t)hrow1 * H2 + hkq1 * 4];
        pw = *(const uint4*)&wsrc[wbase];

        for (int ch = 0; ch < H2 / 32; ch++) {
            {
                uint2 hi, lo; unpack4(ph0, hi, lo);
                *(uint2*)&Hh[hrow][hkq * 4] = hi;
                *(uint2*)&Hl[hrow][hkq * 4] = lo;
                if (has2) {
                    unpack4(ph1, hi, lo);
                    *(uint2*)&Hh[hrow1][hkq1 * 4] = hi;
                    *(uint2*)&Hl[hrow1][hkq1 * 4] = lo;
                }
                if (wishi) *(uint4*)&Wh_[wrow][wkq * 8] = pw;
                else       *(uint4*)&Wl_[wrow][wkq * 8] = pw;
            }
            __syncthreads();

            if (ch + 1 < H2 / 32) {
                const int k0 = (ch + 1) * 32;
                ph0 = *(const uint4*)&ring_rd[(size_t)hrow * H2 + k0 + hkq * 4];
                if (has2) ph1 = *(const uint4*)&ring_rd[(size_t)hrow1 * H2 + k0 + hkq1 * 4];
                pw = *(const uint4*)&wsrc[wbase + k0];
            }

#pragma unroll
            for (int kk16 = 0; kk16 < 2; kk16++) {
                const int kb = kk16 * 16 + 2 * t4;
                unsigned ah[2][4], al[2][4], bh[2], bl[2];
#pragma unroll
                for (int mt = 0; mt < 2; mt++) {
                    int r0 = mh + mt * 16 + g4;
                    ah[mt][0] = *(const unsigned*)&Hh[r0][kb];
                    ah[mt][1] = *(const unsigned*)&Hh[r0 + 8][kb];
                    ah[mt][2] = *(const unsigned*)&Hh[r0][kb + 8];
                    ah[mt][3] = *(const unsigned*)&Hh[r0 + 8][kb + 8];
                    al[mt][0] = *(const unsigned*)&Hl[r0][kb];
                    al[mt][1] = *(const unsigned*)&Hl[r0 + 8][kb];
                    al[mt][2] = *(const unsigned*)&Hl[r0][kb + 8];
                    al[mt][3] = *(const unsigned*)&Hl[r0 + 8][kb + 8];
                }
                int rn = g * 16 + nh + g4;
                bh[0] = *(const unsigned*)&Wh_[rn][kb];
                bh[1] = *(const unsigned*)&Wh_[rn][kb + 8];
                bl[0] = *(const unsigned*)&Wl_[rn][kb];
                bl[1] = *(const unsigned*)&Wl_[rn][kb + 8];
#pragma unroll
                for (int mt = 0; mt < 2; mt++) {
                    mma16816(chi[mt], ah[mt], bh);
                    mma16816(clo[mt], ah[mt], bl);
                    mma16816(clo[mt], al[mt], bh);
                }
            }
            __syncthreads();
        }
    }

#pragma unroll
    for (int mt = 0; mt < 2; mt++) {
        int rm = mh + mt * 16 + g4, cn = nh + 2 * t4;
        gh[g][rm][cn]         = chi[mt][0] + clo[mt][0] * LO_INV;
        gh[g][rm][cn + 1]     = chi[mt][1] + clo[mt][1] * LO_INV;
        gh[g][rm + 8][cn]     = chi[mt][2] + clo[mt][2] * LO_INV;
        gh[g][rm + 8][cn + 1] = chi[mt][3] + clo[mt][3] * LO_INV;
    }
    __syncthreads();

    for (int o = tid; o < 1024; o += 384) {
        int mm = o >> 4, jj = o & 15, j = j0 + jj;
        float r = sigmoidf_(bih[j]          + gh[0][mm][jj] + bhh[j]);
        float z = sigmoidf_(bih[H2 + j]     + gh[1][mm][jj] + bhh[H2 + j]);
        float n = tanhf    (bih[2 * H2 + j] + r * (gh[2][mm][jj] + bhh[2 * H2 + j]));
        float hp = unpackf(ring_rd[(size_t)mm * H2 + j]);
        float hv = (1.0f - z) * n + z * hp;
        __half2 pv = packsplit(hv);
        g_y2d[((size_t)(mm * T + t)) * H2 + j] = pv;
        ring_wr[(size_t)mm * H2 + j] = pv;
    }
}

// ---------------- gather enc_hidden; seed decoder ring buf0 ----------------
__global__ void gather_kernel(const __half2* __restrict__ y2,
                              const int* __restrict__ seq_len,
                              float* __restrict__ out_hid)
{
    int idx = blockIdx.x * 256 + threadIdx.x;   // B*H2
    int b = idx >> 11, k = idx & (H2 - 1);
    int sl = seq_len[b];
    sl = sl < 1 ? 1 : (sl > T ? T : sl);
    __half2 pv = y2[((size_t)(b * T + sl - 1)) * H2 + k];
    out_hid[idx] = unpackf(pv);
    g_dhr[(size_t)b * H2 + k] = pv;
}

// ---------------- host launcher ----------------
extern "C" void kernel_launch(void* const* d_in, const int* in_sizes, int n_in,
                              void* d_out, int out_size)
{
    const float* x    = (const float*)d_in[0];
    const int*   slen = (const int*)  d_in[1];
    const float* Wih0 = (const float*)d_in[2];
    const float* Whh0 = (const float*)d_in[3];
    const float* b0   = (const float*)d_in[4];
    const float* Wih  = (const float*)d_in[5];
    const float* Whh  = (const float*)d_in[6];
    const float* bb   = (const float*)d_in[7];
    const float* dWhh = (const float*)d_in[9];
    const float* db   = (const float*)d_in[10];
    const float* oW   = (const float*)d_in[11];
    const float* ob   = (const float*)d_in[12];
    float* out = (float*)d_out;

    float *p_xg;
    __half2 *p_y2a, *p_y2b, *p_y2d, *p_x2;
    __half *p_W0h, *p_W0l, *p_Wh, *p_Wl, *p_dWh, *p_dWl, *p_Wih_h, *p_Wih_l,
           *p_Wi0h, *p_Wi0l, *p_oWh, *p_oWl;
    cudaGetSymbolAddress((void**)&p_xg, g_xg);
    cudaGetSymbolAddress((void**)&p_y2a, g_y2a);
    cudaGetSymbolAddress((void**)&p_y2b, g_y2b);
    cudaGetSymbolAddress((void**)&p_y2d, g_y2d);
    cudaGetSymbolAddress((void**)&p_x2, g_x2);
    cudaGetSymbolAddress((void**)&p_W0h, s_Whh0h);
    cudaGetSymbolAddress((void**)&p_W0l, s_Whh0l);
    cudaGetSymbolAddress((void**)&p_Wh, s_Whhh);
    cudaGetSymbolAddress((void**)&p_Wl, s_Whhl);
    cudaGetSymbolAddress((void**)&p_dWh, s_dWh);
    cudaGetSymbolAddress((void**)&p_dWl, s_dWl);
    cudaGetSymbolAddress((void**)&p_Wih_h, s_Wihh);
    cudaGetSymbolAddress((void**)&p_Wih_l, s_Wihl);
    cudaGetSymbolAddress((void**)&p_Wi0h, s_Wih0h);
    cudaGetSymbolAddress((void**)&p_Wi0l, s_Wih0l);
    cudaGetSymbolAddress((void**)&p_oWh, s_oWh);
    cudaGetSymbolAddress((void**)&p_oWl, s_oWl);

    // ---- prep: pre-split weights / pack x ----
    k_split<<<2048, 256>>>(Whh0, p_W0h, p_W0l, 2 * G3 * H);
    k_split<<<2048, 256>>>(Whh,  p_Wh,  p_Wl,  4 * G3 * H);
    k_split<<<2048, 256>>>(dWhh, p_dWh, p_dWl, G6 * H2);
    k_split<<<4096, 256>>>(Wih,  p_Wih_h, p_Wih_l, 4 * G3 * H2);
    k_split<<<512,  256>>>(oW,   p_oWh, p_oWl, D * H2);
    k_split_pad<<<512, 256>>>(Wih0, p_Wi0h, p_Wi0l, 2 * G3, D, DP);
    k_pack_pad<<<512, 256>>>(x, p_x2, BT, D, DP);

    const dim3 gG(G3 / 64, BT / 128);
    const dim3 gE(H / 16, 2);
    const int  gDc = H2 / 16;

    // ---- encoder layer 0 (K = 80 padded) ----
    gemm_h2p<<<gG, 256>>>(p_x2, DP, p_Wi0h,                 p_Wi0l,                 b0,        p_xg,      BT, G3, DP, G6);
    gemm_h2p<<<gG, 256>>>(p_x2, DP, p_Wi0h + (size_t)G3*DP, p_Wi0l + (size_t)G3*DP, b0 + 2*G3, p_xg + G3, BT, G3, DP, G6);
    for (int t = 0; t < T; t++)
        enc_step_h3<<<gE, 384>>>(p_W0h, p_W0l, b0 + G3, 2 * G3, p_y2a, t);

    // ---- encoder layer 1 ----
    gemm_h2p<<<gG, 256>>>(p_y2a, H2, p_Wih_h,                 p_Wih_l,                 bb,        p_xg,      BT, G3, H2, G6);
    gemm_h2p<<<gG, 256>>>(p_y2a, H2, p_Wih_h + (size_t)G3*H2, p_Wih_l + (size_t)G3*H2, bb + 2*G3, p_xg + G3, BT, G3, H2, G6);
    for (int t = 0; t < T; t++)
        enc_step_h3<<<gE, 384>>>(p_Wh, p_Wl, bb + G3, 2 * G3, p_y2b, t);

    // ---- encoder layer 2 ----
    gemm_h2p<<<gG, 256>>>(p_y2b, H2, p_Wih_h + (size_t)2*G3*H2, p_Wih_l + (size_t)2*G3*H2, bb + 4*G3, p_xg,      BT, G3, H2, G6);
    gemm_h2p<<<gG, 256>>>(p_y2b, H2, p_Wih_h + (size_t)3*G3*H2, p_Wih_l + (size_t)3*G3*H2, bb + 6*G3, p_xg + G3, BT, G3, H2, G6);
    for (int t = 0; t < T; t++)
        enc_step_h3<<<gE, 384>>>(p_Wh + (size_t)2*G3*H, p_Wl + (size_t)2*G3*H, bb + 5*G3, 2 * G3, p_y2a, t);

    // ---- gather (enc_hidden out + decoder ring seed) ----
    gather_kernel<<<(B * H2) / 256, 256>>>(p_y2a, slen, out);

    // ---- decoder scan ----
    for (int t = 0; t < T; t++)
        dec_step_h3<<<gDc, 384>>>(db, db + G6, t);

    // ---- output projection ----
    gemm_h2p<<<dim3(2, BT / 128), 256>>>(p_y2d, H2, p_oWh, p_oWl, ob,
                                         out + (size_t)B * H2, BT, D, H2, D);
}

// round 7
// speedup vs baseline: 2.4961x; 1.0753x over previous
#include <cuda_runtime.h>
#include <cuda_fp16.h>
#include <math.h>

// Problem dims
#define B   64
#define T   100
#define D   75
#define DP  80      // padded K for layer-0 / x
#define H   1024
#define H2  2048
#define G3  3072
#define G6  6144
#define BT  6400

#define LO_SCALE 4096.0f
#define LO_INV   (1.0f/4096.0f)

// ---------------- scratch (device globals; no allocation) ----------------
__device__ float   g_xg[(size_t)BT * G6];          // input gates (fp32)
__device__ __half2 g_y2a[(size_t)BT * H2];         // layer output ping (packed hi/lo)
__device__ __half2 g_y2b[(size_t)BT * H2];         // layer output pong
__device__ __half2 g_y2d[(size_t)BT * H2];         // decoder hidden sequence
__device__ __half2 g_x2[(size_t)BT * DP];          // packed padded x
__device__ __half2 g_ehr[(size_t)2 * 2 * B * H];   // enc h ring [buf][dir][B][H]
__device__ __half2 g_dhr[(size_t)2 * B * H2];      // dec h ring [buf][B][H2]
// pre-split weight planes (hi / lo*4096)
__device__ __half s_Whh0h[(size_t)2 * G3 * H],  s_Whh0l[(size_t)2 * G3 * H];
__device__ __half s_Whhh [(size_t)4 * G3 * H],  s_Whhl [(size_t)4 * G3 * H];
__device__ __half s_dWh  [(size_t)G6 * H2],     s_dWl  [(size_t)G6 * H2];
__device__ __half s_Wihh [(size_t)4 * G3 * H2], s_Wihl [(size_t)4 * G3 * H2];
__device__ __half s_Wih0h[(size_t)2 * G3 * DP], s_Wih0l[(size_t)2 * G3 * DP];
__device__ __half s_oWh  [(size_t)D * H2],      s_oWl  [(size_t)D * H2];

__device__ __forceinline__ float sigmoidf_(float x) { return 1.0f / (1.0f + __expf(-x)); }

__device__ __forceinline__ __half2 packsplit(float v) {
    __half hi = __float2half_rn(v);
    __half lo = __float2half_rn((v - __half2float(hi)) * LO_SCALE);
    return __halves2half2(hi, lo);
}
__device__ __forceinline__ float unpackf(__half2 p) {
    return __half2float(__low2half(p)) + __half2float(__high2half(p)) * LO_INV;
}

// 4 packed half2 (hi,lo) -> 4 contiguous hi halves + 4 contiguous lo halves
__device__ __forceinline__ void unpack4(uint4 v, uint2& hi, uint2& lo) {
    __half2 a0 = *(__half2*)&v.x, a1 = *(__half2*)&v.y;
    __half2 a2 = *(__half2*)&v.z, a3 = *(__half2*)&v.w;
    __half2 h01 = __lows2half2(a0, a1),  h23 = __lows2half2(a2, a3);
    __half2 l01 = __highs2half2(a0, a1), l23 = __highs2half2(a2, a3);
    hi = make_uint2(*(unsigned*)&h01, *(unsigned*)&h23);
    lo = make_uint2(*(unsigned*)&l01, *(unsigned*)&l23);
}

__device__ __forceinline__ void mma16816(float* c, const unsigned* a, const unsigned* b) {
    asm volatile(
        "mma.sync.aligned.m16n8k16.row.col.f32.f16.f16.f32 "
        "{%0,%1,%2,%3},{%4,%5,%6,%7},{%8,%9},{%0,%1,%2,%3};\n"
        : "+f"(c[0]), "+f"(c[1]), "+f"(c[2]), "+f"(c[3])
        : "r"(a[0]), "r"(a[1]), "r"(a[2]), "r"(a[3]), "r"(b[0]), "r"(b[1]));
}
__device__ __forceinline__ void ldsm4(unsigned* a, unsigned addr) {
    asm volatile("ldmatrix.sync.aligned.m8n8.x4.shared.b16 {%0,%1,%2,%3}, [%4];"
        : "=r"(a[0]), "=r"(a[1]), "=r"(a[2]), "=r"(a[3]) : "r"(addr));
}
__device__ __forceinline__ void ldsm2(unsigned* b, unsigned addr) {
    asm volatile("ldmatrix.sync.aligned.m8n8.x2.shared.b16 {%0,%1}, [%2];"
        : "=r"(b[0]), "=r"(b[1]) : "r"(addr));
}
__device__ __forceinline__ unsigned smaddr(const void* p) {
    return (unsigned)__cvta_generic_to_shared(p);
}

// ================= prep kernels =================
__global__ void k_split(const float* __restrict__ src, __half* __restrict__ hi,
                        __half* __restrict__ lo, int n) {
    for (int i = blockIdx.x * blockDim.x + threadIdx.x; i < n; i += gridDim.x * blockDim.x) {
        float v = src[i];
        __half h = __float2half_rn(v);
        hi[i] = h;
        lo[i] = __float2half_rn((v - __half2float(h)) * LO_SCALE);
    }
}
__global__ void k_split_pad(const float* __restrict__ src, __half* __restrict__ hi,
                            __half* __restrict__ lo, int rows, int kin, int kout) {
    int n = rows * kout;
    for (int i = blockIdx.x * blockDim.x + threadIdx.x; i < n; i += gridDim.x * blockDim.x) {
        int r = i / kout, k = i - r * kout;
        float v = (k < kin) ? src[(size_t)r * kin + k] : 0.0f;
        __half h = __float2half_rn(v);
        hi[i] = h;
        lo[i] = __float2half_rn((v - __half2float(h)) * LO_SCALE);
    }
}
__global__ void k_pack_pad(const float* __restrict__ src, __half2* __restrict__ dst,
                           int rows, int kin, int kout) {
    int n = rows * kout;
    for (int i = blockIdx.x * blockDim.x + threadIdx.x; i < n; i += gridDim.x * blockDim.x) {
        int r = i / kout, k = i - r * kout;
        float v = (k < kin) ? src[(size_t)r * kin + k] : 0.0f;
        dst[i] = packsplit(v);
    }
}

// ================= GEMM: packed-A x pre-split-W, tensor cores (ldmatrix) ====
// C[m,n] = A[m,:]·W[n,:] + bias[n]. Tile 128x64, 8 warps (4M x 2N).
__global__ __launch_bounds__(256) void gemm_h2p(
    const __half2* __restrict__ A2, int lda,
    const __half* __restrict__ Whi, const __half* __restrict__ Wlo,
    const float* __restrict__ bias, float* __restrict__ C,
    int M, int N, int K, int ldc)
{
    __shared__ __half Ah[128][40], Al[128][40];
    __shared__ __half Bh[64][40],  Bl[64][40];

    const int tid = threadIdx.x;
    const int w = tid >> 5, lane = tid & 31;
    const int g4 = lane >> 2, t4 = lane & 3;
    const int m0 = blockIdx.y * 128, n0 = blockIdx.x * 64;
    const int wm = (w >> 1) * 32, wn = (w & 1) * 32;

    const int amm[4] = {(0*256+tid)>>3, (1*256+tid)>>3, (2*256+tid)>>3, (3*256+tid)>>3};
    const int akq = tid & 7;
    const int wnn = tid >> 2, wkq = tid & 3;

    // ldmatrix lane offsets (bytes) within a tile, row stride 80B
    const int lr = lane & 7, lbit8 = (lane >> 3) & 1, lbit16 = (lane >> 4) & 1;
    const int lb = lane & 15, lbr = lb & 7, lbk = (lb >> 3) & 1;
    const unsigned sAh = smaddr(&Ah[0][0]), sAl = smaddr(&Al[0][0]);
    const unsigned sBh = smaddr(&Bh[0][0]), sBl = smaddr(&Bl[0][0]);

    float chi[2][4][4] = {}, clo[2][4][4] = {};
    const int nch = (K + 31) / 32;

    uint4 pa[4], pwh, pwl;
    const uint4 z4 = make_uint4(0, 0, 0, 0);
    {
        const int k0 = 0;
#pragma unroll
        for (int i = 0; i < 4; i++) {
            int gm = m0 + amm[i];
            pa[i] = (gm < M && k0 + akq * 4 < K)
                  ? *(const uint4*)&A2[(size_t)gm * lda + k0 + akq * 4] : z4;
        }
        int gn = n0 + wnn;
        bool okw = (gn < N) && (k0 + wkq * 8 < K);
        size_t wa = (size_t)gn * K + k0 + wkq * 8;
        pwh = okw ? *(const uint4*)&Whi[wa] : z4;
        pwl = okw ? *(const uint4*)&Wlo[wa] : z4;
    }

    for (int ch = 0; ch < nch; ch++) {
#pragma unroll
        for (int i = 0; i < 4; i++) {
            uint2 hi, lo; unpack4(pa[i], hi, lo);
            *(uint2*)&Ah[amm[i]][akq * 4] = hi;
            *(uint2*)&Al[amm[i]][akq * 4] = lo;
        }
        *(uint4*)&Bh[wnn][wkq * 8] = pwh;
        *(uint4*)&Bl[wnn][wkq * 8] = pwl;
        __syncthreads();

        if (ch + 1 < nch) {
            const int k0 = (ch + 1) * 32;
#pragma unroll
            for (int i = 0; i < 4; i++) {
                int gm = m0 + amm[i];
                pa[i] = (gm < M && k0 + akq * 4 < K)
                      ? *(const uint4*)&A2[(size_t)gm * lda + k0 + akq * 4] : z4;
            }
            int gn = n0 + wnn;
            bool okw = (gn < N) && (k0 + wkq * 8 < K);
            size_t wa = (size_t)gn * K + k0 + wkq * 8;
            pwh = okw ? *(const uint4*)&Whi[wa] : z4;
            pwl = okw ? *(const uint4*)&Wlo[wa] : z4;
        }

#pragma unroll
        for (int kk16 = 0; kk16 < 2; kk16++) {
            const int kc2 = kk16 * 32;  // byte offset of k-block
            unsigned ah[2][4], al[2][4], bh[4][2], bl[4][2];
            const unsigned aoff = (unsigned)((wm + lr + lbit8 * 8) * 80 + kc2 + lbit16 * 16);
            const unsigned boff0 = (unsigned)((wn + lbr) * 80 + kc2 + lbk * 16);
#pragma unroll
            for (int mt = 0; mt < 2; mt++) {
                ldsm4(ah[mt], sAh + aoff + mt * 16 * 80);
                ldsm4(al[mt], sAl + aoff + mt * 16 * 80);
            }
#pragma unroll
            for (int nt = 0; nt < 4; nt++) {
                ldsm2(bh[nt], sBh + boff0 + nt * 8 * 80);
                ldsm2(bl[nt], sBl + boff0 + nt * 8 * 80);
            }
#pragma unroll
            for (int mt = 0; mt < 2; mt++)
#pragma unroll
                for (int nt = 0; nt < 4; nt++) {
                    mma16816(chi[mt][nt], ah[mt], bh[nt]);
                    mma16816(clo[mt][nt], ah[mt], bl[nt]);
                    mma16816(clo[mt][nt], al[mt], bh[nt]);
                }
        }
        __syncthreads();
    }

#pragma unroll
    for (int mt = 0; mt < 2; mt++)
#pragma unroll
        for (int nt = 0; nt < 4; nt++) {
            int rm = m0 + wm + mt * 16 + g4;
            int cn = n0 + wn + nt * 8 + 2 * t4;
            const float* ch_ = chi[mt][nt];
            const float* cl_ = clo[mt][nt];
            if (rm < M) {
                if (cn < N)     C[(size_t)rm * ldc + cn]     = ch_[0] + cl_[0] * LO_INV + bias[cn];
                if (cn + 1 < N) C[(size_t)rm * ldc + cn + 1] = ch_[1] + cl_[1] * LO_INV + bias[cn + 1];
            }
            if (rm + 8 < M) {
                if (cn < N)     C[(size_t)(rm + 8) * ldc + cn]     = ch_[2] + cl_[2] * LO_INV + bias[cn];
                if (cn + 1 < N) C[(size_t)(rm + 8) * ldc + cn + 1] = ch_[3] + cl_[3] * LO_INV + bias[cn + 1];
            }
        }
}

// ================= encoder GRU step: 16 j x 3 gates, 12 warps, 2-stage + ldmatrix ====
__global__ __launch_bounds__(384) void enc_step_h4(
    const __half* __restrict__ Whi_all, const __half* __restrict__ Wlo_all,
    const float* __restrict__ bhh_base, int bhh_stride,
    __half2* __restrict__ y2, int t)
{
    const int dir = blockIdx.y;
    const int j0  = blockIdx.x * 16;
    const __half* Whi = Whi_all + (size_t)dir * G3 * H;
    const __half* Wlo = Wlo_all + (size_t)dir * G3 * H;
    const float* bhh = bhh_base + (size_t)dir * bhh_stride;
    const __half2* ring_rd = g_ehr + ((size_t)((t & 1) * 2 + dir)) * B * H;
    __half2*       ring_wr = g_ehr + ((size_t)(((t + 1) & 1) * 2 + dir)) * B * H;

    __shared__ __half Hh[2][64][40], Hl[2][64][40];
    __shared__ __half Wh_[2][48][40], Wl_[2][48][40];
    __shared__ float gh[3][64][16];

    const int tid = threadIdx.x;
    const int w = tid >> 5, lane = tid & 31;
    const int g = w >> 2, mh = ((w >> 1) & 1) * 32, nh = (w & 1) * 8;
    const int g4 = lane >> 2, t4 = lane & 3;

    const int lr = lane & 7, lbit8 = (lane >> 3) & 1, lbit16 = (lane >> 4) & 1;
    const int lb = lane & 15, lbr = lb & 7, lbk = (lb >> 3) & 1;
    const unsigned sHh = smaddr(&Hh[0][0][0]), sHl = smaddr(&Hl[0][0][0]);
    const unsigned sWh = smaddr(&Wh_[0][0][0]), sWl = smaddr(&Wl_[0][0][0]);
    const unsigned HSTG = 64 * 40 * 2, WSTG = 48 * 40 * 2;

    float chi[2][4] = {}, clo[2][4] = {};

    if (t > 0) {
        const int hrow = tid >> 3, hkq = tid & 7;
        const int idx1 = tid + 384;
        const int hrow1 = idx1 >> 3, hkq1 = idx1 & 7;
        const bool has2 = (tid < 128);
        const bool wishi = (tid < 192);
        const int widx = wishi ? tid : tid - 192;
        const int wrow = widx >> 2, wkq = widx & 3;
        const int wg = wrow >> 4, wjj = wrow & 15;
        const size_t wbase = ((size_t)(wg * H + j0 + wjj)) * H + wkq * 8;
        const __half* wsrc = wishi ? Whi : Wlo;

        uint4 ph0, ph1, pw;
        // chunk 0 -> regs -> stage 0
        ph0 = *(const uint4*)&ring_rd[(size_t)hrow * H + hkq * 4];
        if (has2) ph1 = *(const uint4*)&ring_rd[(size_t)hrow1 * H + hkq1 * 4];
        pw = *(const uint4*)&wsrc[wbase];
        {
            uint2 hi, lo; unpack4(ph0, hi, lo);
            *(uint2*)&Hh[0][hrow][hkq * 4] = hi;
            *(uint2*)&Hl[0][hrow][hkq * 4] = lo;
            if (has2) {
                unpack4(ph1, hi, lo);
                *(uint2*)&Hh[0][hrow1][hkq1 * 4] = hi;
                *(uint2*)&Hl[0][hrow1][hkq1 * 4] = lo;
            }
            if (wishi) *(uint4*)&Wh_[0][wrow][wkq * 8] = pw;
            else       *(uint4*)&Wl_[0][wrow][wkq * 8] = pw;
        }

        for (int ch = 0; ch < H / 32; ch++) {
            const int st = ch & 1;
            if (ch + 1 < H / 32) {
                const int k0 = (ch + 1) * 32;
                ph0 = *(const uint4*)&ring_rd[(size_t)hrow * H + k0 + hkq * 4];
                if (has2) ph1 = *(const uint4*)&ring_rd[(size_t)hrow1 * H + k0 + hkq1 * 4];
                pw = *(const uint4*)&wsrc[wbase + k0];
            }
            __syncthreads();   // stage st ready for all warps

            const unsigned bH = st * HSTG, bW = st * WSTG;
#pragma unroll
            for (int kk16 = 0; kk16 < 2; kk16++) {
                const int kc2 = kk16 * 32;
                unsigned ah[2][4], al[2][4], bh[2], bl[2];
                const unsigned aoff = (unsigned)((mh + lr + lbit8 * 8) * 80 + kc2 + lbit16 * 16);
                const unsigned boff = (unsigned)((g * 16 + nh + lbr) * 80 + kc2 + lbk * 16);
                ldsm2(bh, sWh + bW + boff);
                ldsm2(bl, sWl + bW + boff);
#pragma unroll
                for (int mt = 0; mt < 2; mt++) {
                    ldsm4(ah[mt], sHh + bH + aoff + mt * 16 * 80);
                    ldsm4(al[mt], sHl + bH + aoff + mt * 16 * 80);
                }
#pragma unroll
                for (int mt = 0; mt < 2; mt++) {
                    mma16816(chi[mt], ah[mt], bh);
                    mma16816(clo[mt], ah[mt], bl);
                    mma16816(clo[mt], al[mt], bh);
                }
            }

            if (ch + 1 < H / 32) {   // store prefetched chunk to other stage
                const int so = st ^ 1;
                uint2 hi, lo; unpack4(ph0, hi, lo);
                *(uint2*)&Hh[so][hrow][hkq * 4] = hi;
                *(uint2*)&Hl[so][hrow][hkq * 4] = lo;
                if (has2) {
                    unpack4(ph1, hi, lo);
                    *(uint2*)&Hh[so][hrow1][hkq1 * 4] = hi;
                    *(uint2*)&Hl[so][hrow1][hkq1 * 4] = lo;
                }
                if (wishi) *(uint4*)&Wh_[so][wrow][wkq * 8] = pw;
                else       *(uint4*)&Wl_[so][wrow][wkq * 8] = pw;
            }
        }
    }

#pragma unroll
    for (int mt = 0; mt < 2; mt++) {
        int rm = mh + mt * 16 + g4, cn = nh + 2 * t4;
        gh[g][rm][cn]         = chi[mt][0] + clo[mt][0] * LO_INV;
        gh[g][rm][cn + 1]     = chi[mt][1] + clo[mt][1] * LO_INV;
        gh[g][rm + 8][cn]     = chi[mt][2] + clo[mt][2] * LO_INV;
        gh[g][rm + 8][cn + 1] = chi[mt][3] + clo[mt][3] * LO_INV;
    }
    __syncthreads();

    for (int o = tid; o < 1024; o += 384) {
        int mm = o >> 4, jj = o & 15, j = j0 + jj;
        const float* xgp = g_xg + (size_t)(mm * T + t) * G6 + dir * G3;
        float r = sigmoidf_(xgp[j]         + gh[0][mm][jj] + bhh[j]);
        float z = sigmoidf_(xgp[H + j]     + gh[1][mm][jj] + bhh[H + j]);
        float n = tanhf    (xgp[2 * H + j] + r * (gh[2][mm][jj] + bhh[2 * H + j]));
        float hp = (t == 0) ? 0.0f : unpackf(ring_rd[(size_t)mm * H + j]);
        float hv = (1.0f - z) * n + z * hp;
        __half2 pv = packsplit(hv);
        y2[((size_t)(mm * T + t)) * H2 + dir * H + j] = pv;
        ring_wr[(size_t)mm * H + j] = pv;
    }
}

// ================= decoder GRU step (2-stage + ldmatrix) =================
__global__ __launch_bounds__(384) void dec_step_h4(
    const float* __restrict__ bih, const float* __restrict__ bhh, int t)
{
    const int j0 = blockIdx.x * 16;
    const __half2* ring_rd = g_dhr + ((size_t)(t & 1)) * B * H2;
    __half2*       ring_wr = g_dhr + ((size_t)((t + 1) & 1)) * B * H2;

    __shared__ __half Hh[2][64][40], Hl[2][64][40];
    __shared__ __half Wh_[2][48][40], Wl_[2][48][40];
    __shared__ float gh[3][64][16];

    const int tid = threadIdx.x;
    const int w = tid >> 5, lane = tid & 31;
    const int g = w >> 2, mh = ((w >> 1) & 1) * 32, nh = (w & 1) * 8;
    const int g4 = lane >> 2, t4 = lane & 3;

    const int lr = lane & 7, lbit8 = (lane >> 3) & 1, lbit16 = (lane >> 4) & 1;
    const int lb = lane & 15, lbr = lb & 7, lbk = (lb >> 3) & 1;
    const unsigned sHh = smaddr(&Hh[0][0][0]), sHl = smaddr(&Hl[0][0][0]);
    const unsigned sWh = smaddr(&Wh_[0][0][0]), sWl = smaddr(&Wl_[0][0][0]);
    const unsigned HSTG = 64 * 40 * 2, WSTG = 48 * 40 * 2;

    float chi[2][4] = {}, clo[2][4] = {};

    {
        const int hrow = tid >> 3, hkq = tid & 7;
        const int idx1 = tid + 384;
        const int hrow1 = idx1 >> 3, hkq1 = idx1 & 7;
        const bool has2 = (tid < 128);
        const bool wishi = (tid < 192);
        const int widx = wishi ? tid : tid - 192;
        const int wrow = widx >> 2, wkq = widx & 3;
        const int wg = wrow >> 4, wjj = wrow & 15;
        const size_t wbase = ((size_t)(wg * H2 + j0 + wjj)) * H2 + wkq * 8;
        const __half* wsrc = wishi ? s_dWh : s_dWl;

        uint4 ph0, ph1, pw;
        ph0 = *(const uint4*)&ring_rd[(size_t)hrow * H2 + hkq * 4];
        if (has2) ph1 = *(const uint4*)&ring_rd[(size_t)hrow1 * H2 + hkq1 * 4];
        pw = *(const uint4*)&wsrc[wbase];
        {
            uint2 hi, lo; unpack4(ph0, hi, lo);
            *(uint2*)&Hh[0][hrow][hkq * 4] = hi;
            *(uint2*)&Hl[0][hrow][hkq * 4] = lo;
            if (has2) {
                unpack4(ph1, hi, lo);
                *(uint2*)&Hh[0][hrow1][hkq1 * 4] = hi;
                *(uint2*)&Hl[0][hrow1][hkq1 * 4] = lo;
            }
            if (wishi) *(uint4*)&Wh_[0][wrow][wkq * 8] = pw;
            else       *(uint4*)&Wl_[0][wrow][wkq * 8] = pw;
        }

        for (int ch = 0; ch < H2 / 32; ch++) {
            const int st = ch & 1;
            if (ch + 1 < H2 / 32) {
                const int k0 = (ch + 1) * 32;
                ph0 = *(const uint4*)&ring_rd[(size_t)hrow * H2 + k0 + hkq * 4];
                if (has2) ph1 = *(const uint4*)&ring_rd[(size_t)hrow1 * H2 + k0 + hkq1 * 4];
                pw = *(const uint4*)&wsrc[wbase + k0];
            }
            __syncthreads();

            const unsigned bH = st * HSTG, bW = st * WSTG;
#pragma unroll
            for (int kk16 = 0; kk16 < 2; kk16++) {
                const int kc2 = kk16 * 32;
                unsigned ah[2][4], al[2][4], bh[2], bl[2];
                const unsigned aoff = (unsigned)((mh + lr + lbit8 * 8) * 80 + kc2 + lbit16 * 16);
                const unsigned boff = (unsigned)((g * 16 + nh + lbr) * 80 + kc2 + lbk * 16);
                ldsm2(bh, sWh + bW + boff);
                ldsm2(bl, sWl + bW + boff);
#pragma unroll
                for (int mt = 0; mt < 2; mt++) {
                    ldsm4(ah[mt], sHh + bH + aoff + mt * 16 * 80);
                    ldsm4(al[mt], sHl + bH + aoff + mt * 16 * 80);
                }
#pragma unroll
                for (int mt = 0; mt < 2; mt++) {
                    mma16816(chi[mt], ah[mt], bh);
                    mma16816(clo[mt], ah[mt], bl);
                    mma16816(clo[mt], al[mt], bh);
                }
            }

            if (ch + 1 < H2 / 32) {
                const int so = st ^ 1;
                uint2 hi, lo; unpack4(ph0, hi, lo);
                *(uint2*)&Hh[so][hrow][hkq * 4] = hi;
                *(uint2*)&Hl[so][hrow][hkq * 4] = lo;
                if (has2) {
                    unpack4(ph1, hi, lo);
                    *(uint2*)&Hh[so][hrow1][hkq1 * 4] = hi;
                    *(uint2*)&Hl[so][hrow1][hkq1 * 4] = lo;
                }
                if (wishi) *(uint4*)&Wh_[so][wrow][wkq * 8] = pw;
                else       *(uint4*)&Wl_[so][wrow][wkq * 8] = pw;
            }
        }
    }

#pragma unroll
    for (int mt = 0; mt < 2; mt++) {
        int rm = mh + mt * 16 + g4, cn = nh + 2 * t4;
        gh[g][rm][cn]         = chi[mt][0] + clo[mt][0] * LO_INV;
        gh[g][rm][cn + 1]     = chi[mt][1] + clo[mt][1] * LO_INV;
        gh[g][rm + 8][cn]     = chi[mt][2] + clo[mt][2] * LO_INV;
        gh[g][rm + 8][cn + 1] = chi[mt][3] + clo[mt][3] * LO_INV;
    }
    __syncthreads();

    for (int o = tid; o < 1024; o += 384) {
        int mm = o >> 4, jj = o & 15, j = j0 + jj;
        float r = sigmoidf_(bih[j]          + gh[0][mm][jj] + bhh[j]);
        float z = sigmoidf_(bih[H2 + j]     + gh[1][mm][jj] + bhh[H2 + j]);
        float n = tanhf    (bih[2 * H2 + j] + r * (gh[2][mm][jj] + bhh[2 * H2 + j]));
        float hp = unpackf(ring_rd[(size_t)mm * H2 + j]);
        float hv = (1.0f - z) * n + z * hp;
        __half2 pv = packsplit(hv);
        g_y2d[((size_t)(mm * T + t)) * H2 + j] = pv;
        ring_wr[(size_t)mm * H2 + j] = pv;
    }
}

// ---------------- gather enc_hidden; seed decoder ring buf0 ----------------
__global__ void gather_kernel(const __half2* __restrict__ y2,
                              const int* __restrict__ seq_len,
                              float* __restrict__ out_hid)
{
    int idx = blockIdx.x * 256 + threadIdx.x;   // B*H2
    int b = idx >> 11, k = idx & (H2 - 1);
    int sl = seq_len[b];
    sl = sl < 1 ? 1 : (sl > T ? T : sl);
    __half2 pv = y2[((size_t)(b * T + sl - 1)) * H2 + k];
    out_hid[idx] = unpackf(pv);
    g_dhr[(size_t)b * H2 + k] = pv;
}

// ---------------- host launcher ----------------
extern "C" void kernel_launch(void* const* d_in, const int* in_sizes, int n_in,
                              void* d_out, int out_size)
{
    const float* x    = (const float*)d_in[0];
    const int*   slen = (const int*)  d_in[1];
    const float* Wih0 = (const float*)d_in[2];
    const float* Whh0 = (const float*)d_in[3];
    const float* b0   = (const float*)d_in[4];
    const float* Wih  = (const float*)d_in[5];
    const float* Whh  = (const float*)d_in[6];
    const float* bb   = (const float*)d_in[7];
    const float* dWhh = (const float*)d_in[9];
    const float* db   = (const float*)d_in[10];
    const float* oW   = (const float*)d_in[11];
    const float* ob   = (const float*)d_in[12];
    float* out = (float*)d_out;

    float *p_xg;
    __half2 *p_y2a, *p_y2b, *p_y2d, *p_x2;
    __half *p_W0h, *p_W0l, *p_Wh, *p_Wl, *p_dWh, *p_dWl, *p_Wih_h, *p_Wih_l,
           *p_Wi0h, *p_Wi0l, *p_oWh, *p_oWl;
    cudaGetSymbolAddress((void**)&p_xg, g_xg);
    cudaGetSymbolAddress((void**)&p_y2a, g_y2a);
    cudaGetSymbolAddress((void**)&p_y2b, g_y2b);
    cudaGetSymbolAddress((void**)&p_y2d, g_y2d);
    cudaGetSymbolAddress((void**)&p_x2, g_x2);
    cudaGetSymbolAddress((void**)&p_W0h, s_Whh0h);
    cudaGetSymbolAddress((void**)&p_W0l, s_Whh0l);
    cudaGetSymbolAddress((void**)&p_Wh, s_Whhh);
    cudaGetSymbolAddress((void**)&p_Wl, s_Whhl);
    cudaGetSymbolAddress((void**)&p_dWh, s_dWh);
    cudaGetSymbolAddress((void**)&p_dWl, s_dWl);
    cudaGetSymbolAddress((void**)&p_Wih_h, s_Wihh);
    cudaGetSymbolAddress((void**)&p_Wih_l, s_Wihl);
    cudaGetSymbolAddress((void**)&p_Wi0h, s_Wih0h);
    cudaGetSymbolAddress((void**)&p_Wi0l, s_Wih0l);
    cudaGetSymbolAddress((void**)&p_oWh, s_oWh);
    cudaGetSymbolAddress((void**)&p_oWl, s_oWl);

    // ---- prep: pre-split weights / pack x ----
    k_split<<<2048, 256>>>(Whh0, p_W0h, p_W0l, 2 * G3 * H);
    k_split<<<2048, 256>>>(Whh,  p_Wh,  p_Wl,  4 * G3 * H);
    k_split<<<2048, 256>>>(dWhh, p_dWh, p_dWl, G6 * H2);
    k_split<<<4096, 256>>>(Wih,  p_Wih_h, p_Wih_l, 4 * G3 * H2);
    k_split<<<512,  256>>>(oW,   p_oWh, p_oWl, D * H2);
    k_split_pad<<<512, 256>>>(Wih0, p_Wi0h, p_Wi0l, 2 * G3, D, DP);
    k_pack_pad<<<512, 256>>>(x, p_x2, BT, D, DP);

    const dim3 gG(G3 / 64, BT / 128);
    const dim3 gE(H / 16, 2);
    const int  gDc = H2 / 16;

    // ---- encoder layer 0 (K = 80 padded) ----
    gemm_h2p<<<gG, 256>>>(p_x2, DP, p_Wi0h,                 p_Wi0l,                 b0,        p_xg,      BT, G3, DP, G6);
    gemm_h2p<<<gG, 256>>>(p_x2, DP, p_Wi0h + (size_t)G3*DP, p_Wi0l + (size_t)G3*DP, b0 + 2*G3, p_xg + G3, BT, G3, DP, G6);
    for (int t = 0; t < T; t++)
        enc_step_h4<<<gE, 384>>>(p_W0h, p_W0l, b0 + G3, 2 * G3, p_y2a, t);

    // ---- encoder layer 1 ----
    gemm_h2p<<<gG, 256>>>(p_y2a, H2, p_Wih_h,                 p_Wih_l,                 bb,        p_xg,      BT, G3, H2, G6);
    gemm_h2p<<<gG, 256>>>(p_y2a, H2, p_Wih_h + (size_t)G3*H2, p_Wih_l + (size_t)G3*H2, bb + 2*G3, p_xg + G3, BT, G3, H2, G6);
    for (int t = 0; t < T; t++)
        enc_step_h4<<<gE, 384>>>(p_Wh, p_Wl, bb + G3, 2 * G3, p_y2b, t);

    // ---- encoder layer 2 ----
    gemm_h2p<<<gG, 256>>>(p_y2b, H2, p_Wih_h + (size_t)2*G3*H2, p_Wih_l + (size_t)2*G3*H2, bb + 4*G3, p_xg,      BT, G3, H2, G6);
    gemm_h2p<<<gG, 256>>>(p_y2b, H2, p_Wih_h + (size_t)3*G3*H2, p_Wih_l + (size_t)3*G3*H2, bb + 6*G3, p_xg + G3, BT, G3, H2, G6);
    for (int t = 0; t < T; t++)
        enc_step_h4<<<gE, 384>>>(p_Wh + (size_t)2*G3*H, p_Wl + (size_t)2*G3*H, bb + 5*G3, 2 * G3, p_y2a, t);

    // ---- gather (enc_hidden out + decoder ring seed) ----
    gather_kernel<<<(B * H2) / 256, 256>>>(p_y2a, slen, out);

    // ---- decoder scan ----
    for (int t = 0; t < T; t++)
        dec_step_h4<<<gDc, 384>>>(db, db + G6, t);

    // ---- output projection ----
    gemm_h2p<<<dim3(2, BT / 128), 256>>>(p_y2d, H2, p_oWh, p_oWl, ob,
                                         out + (size_t)B * H2, BT, D, H2, D);
}

// round 10
// speedup vs baseline: 2.5544x; 1.0233x over previous
#include <cuda_runtime.h>
#include <cuda_fp16.h>
#include <math.h>

// Problem dims
#define B   64
#define T   100
#define D   75
#define DP  80      // padded K for layer-0 / x
#define H   1024
#define H2  2048
#define G3  3072
#define G6  6144
#define BT  6400

#define LO_SCALE 4096.0f
#define LO_INV   (1.0f/4096.0f)

// ---------------- scratch (device globals; no allocation) ----------------
__device__ float  g_xg[(size_t)BT * G6];           // input gates (fp32)
// layer outputs / decoder hidden as dual half planes (hi, lo*4096)
__device__ __half g_yha[(size_t)BT * H2], g_yla[(size_t)BT * H2];
__device__ __half g_yhb[(size_t)BT * H2], g_ylb[(size_t)BT * H2];
__device__ __half g_yhd[(size_t)BT * H2], g_yld[(size_t)BT * H2];
__device__ __half g_xh[(size_t)BT * DP],  g_xl[(size_t)BT * DP];
__device__ __half g_ehrh[(size_t)2*2*B*H],  g_ehrl[(size_t)2*2*B*H];   // enc ring [buf][dir][B][H]
__device__ __half g_dhrh[(size_t)2*B*H2],   g_dhrl[(size_t)2*B*H2];    // dec ring [buf][B][H2]
// pre-split weight planes
__device__ __half s_Whh0h[(size_t)2*G3*H],  s_Whh0l[(size_t)2*G3*H];
__device__ __half s_Whhh [(size_t)4*G3*H],  s_Whhl [(size_t)4*G3*H];
__device__ __half s_dWh  [(size_t)G6*H2],   s_dWl  [(size_t)G6*H2];
__device__ __half s_Wihh [(size_t)4*G3*H2], s_Wihl [(size_t)4*G3*H2];
__device__ __half s_Wih0h[(size_t)2*G3*DP], s_Wih0l[(size_t)2*G3*DP];
__device__ __half s_oWh  [(size_t)D*H2],    s_oWl  [(size_t)D*H2];

__device__ __forceinline__ float sigmoidf_(float x) { return 1.0f / (1.0f + __expf(-x)); }

__device__ __forceinline__ void splitf(float v, __half& hi, __half& lo) {
    hi = __float2half_rn(v);
    lo = __float2half_rn((v - __half2float(hi)) * LO_SCALE);
}

__device__ __forceinline__ void mma16816(float* c, const unsigned* a, const unsigned* b) {
    asm volatile(
        "mma.sync.aligned.m16n8k16.row.col.f32.f16.f16.f32 "
        "{%0,%1,%2,%3},{%4,%5,%6,%7},{%8,%9},{%0,%1,%2,%3};\n"
        : "+f"(c[0]), "+f"(c[1]), "+f"(c[2]), "+f"(c[3])
        : "r"(a[0]), "r"(a[1]), "r"(a[2]), "r"(a[3]), "r"(b[0]), "r"(b[1]));
}
__device__ __forceinline__ void ldsm4(unsigned* a, unsigned addr) {
    asm volatile("ldmatrix.sync.aligned.m8n8.x4.shared.b16 {%0,%1,%2,%3}, [%4];"
        : "=r"(a[0]), "=r"(a[1]), "=r"(a[2]), "=r"(a[3]) : "r"(addr));
}
__device__ __forceinline__ void ldsm2(unsigned* b, unsigned addr) {
    asm volatile("ldmatrix.sync.aligned.m8n8.x2.shared.b16 {%0,%1}, [%2];"
        : "=r"(b[0]), "=r"(b[1]) : "r"(addr));
}
__device__ __forceinline__ unsigned smaddr(const void* p) {
    return (unsigned)__cvta_generic_to_shared(p);
}
__device__ __forceinline__ void cpa16(unsigned dst, const void* src) {
    asm volatile("cp.async.cg.shared.global [%0], [%1], 16;" :: "r"(dst), "l"(src));
}
__device__ __forceinline__ void cpa_commit() {
    asm volatile("cp.async.commit_group;" ::: "memory");
}
__device__ __forceinline__ void cpa_wait2() {
    asm volatile("cp.async.wait_group 2;" ::: "memory");
}

// ================= prep kernels =================
__global__ void k_split(const float* __restrict__ src, __half* __restrict__ hi,
                        __half* __restrict__ lo, int n) {
    for (int i = blockIdx.x * blockDim.x + threadIdx.x; i < n; i += gridDim.x * blockDim.x) {
        __half h, l; splitf(src[i], h, l);
        hi[i] = h; lo[i] = l;
    }
}
__global__ void k_split_pad(const float* __restrict__ src, __half* __restrict__ hi,
                            __half* __restrict__ lo, int rows, int kin, int kout) {
    int n = rows * kout;
    for (int i = blockIdx.x * blockDim.x + threadIdx.x; i < n; i += gridDim.x * blockDim.x) {
        int r = i / kout, k = i - r * kout;
        float v = (k < kin) ? src[(size_t)r * kin + k] : 0.0f;
        __half h, l; splitf(v, h, l);
        hi[i] = h; lo[i] = l;
    }
}

// ================= GEMM: dual-plane A x pre-split W (ldmatrix) =================
// C[m,n] = A[m,:]·W[n,:] + bias[n]. Tile 128x64, 8 warps (4M x 2N).
__global__ __launch_bounds__(256) void gemm_h2p(
    const __half* __restrict__ Ahi, const __half* __restrict__ Alo, int lda,
    const __half* __restrict__ Whi, const __half* __restrict__ Wlo,
    const float* __restrict__ bias, float* __restrict__ C,
    int M, int N, int K, int ldc)
{
    __shared__ __half Ah[128][40], Al[128][40];
    __shared__ __half Bh[64][40],  Bl[64][40];

    const int tid = threadIdx.x;
    const int w = tid >> 5, lane = tid & 31;
    const int g4 = lane >> 2, t4 = lane & 3;
    const int m0 = blockIdx.y * 128, n0 = blockIdx.x * 64;
    const int wm = (w >> 1) * 32, wn = (w & 1) * 32;

    const int ar[2]  = {(0*256+tid)>>2, (1*256+tid)>>2};
    const int asg[2] = {(0*256+tid)&3,  (1*256+tid)&3};
    const int bidx[2] = {0*256+tid, 1*256+tid};

    const int lr = lane & 7, lbit8 = (lane >> 3) & 1, lbit16 = (lane >> 4) & 1;
    const int lb = lane & 15, lbr = lb & 7, lbk = (lb >> 3) & 1;
    const unsigned sAh = smaddr(&Ah[0][0]), sAl = smaddr(&Al[0][0]);
    const unsigned sBh = smaddr(&Bh[0][0]), sBl = smaddr(&Bl[0][0]);

    float chi[2][4][4] = {}, clo[2][4][4] = {};
    const int nch = (K + 31) / 32;

    uint4 pah[2], pal[2], pb[2];
    const uint4 z4 = make_uint4(0, 0, 0, 0);

    auto loadA = [&](int k0) {
#pragma unroll
        for (int i = 0; i < 2; i++) {
            int gm = m0 + ar[i], gk = k0 + asg[i] * 8;
            bool ok = (gm < M) && (gk < K);
            pah[i] = ok ? *(const uint4*)&Ahi[(size_t)gm * lda + gk] : z4;
            pal[i] = ok ? *(const uint4*)&Alo[(size_t)gm * lda + gk] : z4;
        }
    };
    auto loadB = [&](int k0) {
#pragma unroll
        for (int i = 0; i < 2; i++) {
            int idx = bidx[i], pl = idx >> 8, wi = idx & 255;
            int gn = n0 + (wi >> 2), gk = k0 + (wi & 3) * 8;
            bool ok = (gn < N) && (gk < K);
            const __half* src = pl ? Wlo : Whi;
            pb[i] = ok ? *(const uint4*)&src[(size_t)gn * K + gk] : z4;
        }
    };
    auto storeAB = [&]() {
#pragma unroll
        for (int i = 0; i < 2; i++) {
            *(uint4*)&Ah[ar[i]][asg[i] * 8] = pah[i];
            *(uint4*)&Al[ar[i]][asg[i] * 8] = pal[i];
        }
#pragma unroll
        for (int i = 0; i < 2; i++) {
            int idx = bidx[i], pl = idx >> 8, wi = idx & 255;
            if (pl) *(uint4*)&Bl[wi >> 2][(wi & 3) * 8] = pb[i];
            else    *(uint4*)&Bh[wi >> 2][(wi & 3) * 8] = pb[i];
        }
    };

    loadA(0); loadB(0);
    for (int ch = 0; ch < nch; ch++) {
        storeAB();
        __syncthreads();
        if (ch + 1 < nch) { loadA((ch + 1) * 32); loadB((ch + 1) * 32); }

#pragma unroll
        for (int kk16 = 0; kk16 < 2; kk16++) {
            const int kc2 = kk16 * 32;
            unsigned ah[2][4], al[2][4], bh[4][2], bl[4][2];
            const unsigned aoff = (unsigned)((wm + lr + lbit8 * 8) * 80 + kc2 + lbit16 * 16);
            const unsigned boff0 = (unsigned)((wn + lbr) * 80 + kc2 + lbk * 16);
#pragma unroll
            for (int mt = 0; mt < 2; mt++) {
                ldsm4(ah[mt], sAh + aoff + mt * 16 * 80);
                ldsm4(al[mt], sAl + aoff + mt * 16 * 80);
            }
#pragma unroll
            for (int nt = 0; nt < 4; nt++) {
                ldsm2(bh[nt], sBh + boff0 + nt * 8 * 80);
                ldsm2(bl[nt], sBl + boff0 + nt * 8 * 80);
            }
#pragma unroll
            for (int mt = 0; mt < 2; mt++)
#pragma unroll
                for (int nt = 0; nt < 4; nt++) {
                    mma16816(chi[mt][nt], ah[mt], bh[nt]);
                    mma16816(clo[mt][nt], ah[mt], bl[nt]);
                    mma16816(clo[mt][nt], al[mt], bh[nt]);
                }
        }
        __syncthreads();
    }

#pragma unroll
    for (int mt = 0; mt < 2; mt++)
#pragma unroll
        for (int nt = 0; nt < 4; nt++) {
            int rm = m0 + wm + mt * 16 + g4;
            int cn = n0 + wn + nt * 8 + 2 * t4;
            const float* ch_ = chi[mt][nt];
            const float* cl_ = clo[mt][nt];
            if (rm < M) {
                if (cn < N)     C[(size_t)rm * ldc + cn]     = ch_[0] + cl_[0] * LO_INV + bias[cn];
                if (cn + 1 < N) C[(size_t)rm * ldc + cn + 1] = ch_[1] + cl_[1] * LO_INV + bias[cn + 1];
            }
            if (rm + 8 < M) {
                if (cn < N)     C[(size_t)(rm + 8) * ldc + cn]     = ch_[2] + cl_[2] * LO_INV + bias[cn];
                if (cn + 1 < N) C[(size_t)(rm + 8) * ldc + cn + 1] = ch_[3] + cl_[3] * LO_INV + bias[cn + 1];
            }
        }
}

// ======= step-kernel shared constants (dynamic smem, 4-stage cp.async ring) =======
#define HPL (64 * 40)            // halves per H plane per stage
#define WPL (48 * 40)
#define HSTB (HPL * 2)           // bytes
#define WSTB (WPL * 2)
#define SMEM_STEP (4 * (2*HSTB + 2*WSTB) + 3 * 64 * 16 * 4)   // 83968

// ================= encoder GRU step =================
__global__ __launch_bounds__(384) void enc_step_h5(
    const __half* __restrict__ Whi_all, const __half* __restrict__ Wlo_all,
    const float* __restrict__ bhh_base, int bhh_stride,
    __half* __restrict__ yh, __half* __restrict__ yl, int t)
{
    extern __shared__ char dsm[];
    __half* Hh = (__half*)dsm;               // [4][64][40]
    __half* Hl = Hh + 4 * HPL;
    __half* Wh = Hl + 4 * HPL;               // [4][48][40]
    __half* Wl = Wh + 4 * WPL;
    float*  gh = (float*)(Wl + 4 * WPL);     // [3][64][16]

    const int dir = blockIdx.y;
    const int j0  = blockIdx.x * 16;
    const __half* Whi = Whi_all + (size_t)dir * G3 * H;
    const __half* Wlo = Wlo_all + (size_t)dir * G3 * H;
    const float* bhh = bhh_base + (size_t)dir * bhh_stride;
    const __half* rrh = g_ehrh + ((size_t)((t & 1) * 2 + dir)) * B * H;
    const __half* rrl = g_ehrl + ((size_t)((t & 1) * 2 + dir)) * B * H;
    __half* rwh = g_ehrh + ((size_t)(((t + 1) & 1) * 2 + dir)) * B * H;
    __half* rwl = g_ehrl + ((size_t)(((t + 1) & 1) * 2 + dir)) * B * H;

    const int tid = threadIdx.x;
    const int w = tid >> 5, lane = tid & 31;
    const int g = w >> 2, mh = ((w >> 1) & 1) * 32, nh = (w & 1) * 8;
    const int g4 = lane >> 2, t4 = lane & 3;

    const int lr = lane & 7, lbit8 = (lane >> 3) & 1, lbit16 = (lane >> 4) & 1;
    const int lb = lane & 15, lbr = lb & 7, lbk = (lb >> 3) & 1;
    const unsigned sHh = smaddr(Hh), sHl = smaddr(Hl);
    const unsigned sWh = smaddr(Wh), sWl = smaddr(Wl);

    float chi[2][4] = {}, clo[2][4] = {};

    if (t > 0) {
        const int wpl = tid >= 192;
        const int widx = wpl ? tid - 192 : tid;
        const int wr = widx >> 2, wsg = widx & 3;
        const int wgate = wr >> 4, wjj = wr & 15;
        const size_t wgoff = ((size_t)(wgate * H + j0 + wjj)) * H + wsg * 8;
        const __half* wsrc = wpl ? Wlo : Whi;
        const unsigned wdst0 = (wpl ? sWl : sWh) + (unsigned)(wr * 80 + wsg * 16);

        auto issue = [&](int st, int k0) {
#pragma unroll
            for (int i = 0; i < 2; i++) {
                int s = tid + i * 384;
                if (s < 512) {
                    int pl = s >> 8, r = (s & 255) >> 2, sg = s & 3;
                    unsigned dst = (pl ? sHl : sHh) + (unsigned)(st * HSTB + r * 80 + sg * 16);
                    const __half* src = (pl ? rrl : rrh) + (size_t)r * H + k0 + sg * 8;
                    cpa16(dst, src);
                }
            }
            cpa16(wdst0 + st * WSTB, wsrc + wgoff + k0);
        };

        issue(0, 0); cpa_commit();
        issue(1, 32); cpa_commit();
        issue(2, 64); cpa_commit();

        for (int ch = 0; ch < H / 32; ch++) {
            cpa_wait2();
            __syncthreads();
            const int st = ch & 3;
            const unsigned bH = st * HSTB, bW = st * WSTB;
#pragma unroll
            for (int kk16 = 0; kk16 < 2; kk16++) {
                const int kc2 = kk16 * 32;
                unsigned ah[2][4], al[2][4], bh[2], bl[2];
                const unsigned aoff = (unsigned)((mh + lr + lbit8 * 8) * 80 + kc2 + lbit16 * 16);
                const unsigned boff = (unsigned)((g * 16 + nh + lbr) * 80 + kc2 + lbk * 16);
                ldsm2(bh, sWh + bW + boff);
                ldsm2(bl, sWl + bW + boff);
#pragma unroll
                for (int mt = 0; mt < 2; mt++) {
                    ldsm4(ah[mt], sHh + bH + aoff + mt * 16 * 80);
                    ldsm4(al[mt], sHl + bH + aoff + mt * 16 * 80);
                }
#pragma unroll
                for (int mt = 0; mt < 2; mt++) {
                    mma16816(chi[mt], ah[mt], bh);
                    mma16816(clo[mt], ah[mt], bl);
                    mma16816(clo[mt], al[mt], bh);
                }
            }
            if (ch + 3 < H / 32) issue((ch + 3) & 3, (ch + 3) * 32);
            cpa_commit();
        }
    }

#pragma unroll
    for (int mt = 0; mt < 2; mt++) {
        int rm = mh + mt * 16 + g4, cn = nh + 2 * t4;
        gh[(g * 64 + rm) * 16 + cn]           = chi[mt][0] + clo[mt][0] * LO_INV;
        gh[(g * 64 + rm) * 16 + cn + 1]       = chi[mt][1] + clo[mt][1] * LO_INV;
        gh[(g * 64 + rm + 8) * 16 + cn]       = chi[mt][2] + clo[mt][2] * LO_INV;
        gh[(g * 64 + rm + 8) * 16 + cn + 1]   = chi[mt][3] + clo[mt][3] * LO_INV;
    }
    __syncthreads();

    for (int o = tid; o < 1024; o += 384) {
        int mm = o >> 4, jj = o & 15, j = j0 + jj;
        const float* xgp = g_xg + (size_t)(mm * T + t) * G6 + dir * G3;
        float r = sigmoidf_(xgp[j]         + gh[(0 * 64 + mm) * 16 + jj] + bhh[j]);
        float z = sigmoidf_(xgp[H + j]     + gh[(1 * 64 + mm) * 16 + jj] + bhh[H + j]);
        float n = tanhf    (xgp[2 * H + j] + r * (gh[(2 * 64 + mm) * 16 + jj] + bhh[2 * H + j]));
        float hp = (t == 0) ? 0.0f
                 : __half2float(rrh[(size_t)mm * H + j]) + __half2float(rrl[(size_t)mm * H + j]) * LO_INV;
        float hv = (1.0f - z) * n + z * hp;
        __half phi, plo; splitf(hv, phi, plo);
        size_t oi = ((size_t)(mm * T + t)) * H2 + dir * H + j;
        yh[oi] = phi; yl[oi] = plo;
        rwh[(size_t)mm * H + j] = phi; rwl[(size_t)mm * H + j] = plo;
    }
}

// ================= decoder GRU step =================
__global__ __launch_bounds__(384) void dec_step_h5(
    const float* __restrict__ bih, const float* __restrict__ bhh, int t)
{
    extern __shared__ char dsm[];
    __half* Hh = (__half*)dsm;
    __half* Hl = Hh + 4 * HPL;
    __half* Wh = Hl + 4 * HPL;
    __half* Wl = Wh + 4 * WPL;
    float*  gh = (float*)(Wl + 4 * WPL);

    const int j0 = blockIdx.x * 16;
    const __half* rrh = g_dhrh + ((size_t)(t & 1)) * B * H2;
    const __half* rrl = g_dhrl + ((size_t)(t & 1)) * B * H2;
    __half* rwh = g_dhrh + ((size_t)((t + 1) & 1)) * B * H2;
    __half* rwl = g_dhrl + ((size_t)((t + 1) & 1)) * B * H2;

    const int tid = threadIdx.x;
    const int w = tid >> 5, lane = tid & 31;
    const int g = w >> 2, mh = ((w >> 1) & 1) * 32, nh = (w & 1) * 8;
    const int g4 = lane >> 2, t4 = lane & 3;

    const int lr = lane & 7, lbit8 = (lane >> 3) & 1, lbit16 = (lane >> 4) & 1;
    const int lb = lane & 15, lbr = lb & 7, lbk = (lb >> 3) & 1;
    const unsigned sHh = smaddr(Hh), sHl = smaddr(Hl);
    const unsigned sWh = smaddr(Wh), sWl = smaddr(Wl);

    float chi[2][4] = {}, clo[2][4] = {};

    {
        const int wpl = tid >= 192;
        const int widx = wpl ? tid - 192 : tid;
        const int wr = widx >> 2, wsg = widx & 3;
        const int wgate = wr >> 4, wjj = wr & 15;
        const size_t wgoff = ((size_t)(wgate * H2 + j0 + wjj)) * H2 + wsg * 8;
        const __half* wsrc = wpl ? s_dWl : s_dWh;
        const unsigned wdst0 = (wpl ? sWl : sWh) + (unsigned)(wr * 80 + wsg * 16);

        auto issue = [&](int st, int k0) {
#pragma unroll
            for (int i = 0; i < 2; i++) {
                int s = tid + i * 384;
                if (s < 512) {
                    int pl = s >> 8, r = (s & 255) >> 2, sg = s & 3;
                    unsigned dst = (pl ? sHl : sHh) + (unsigned)(st * HSTB + r * 80 + sg * 16);
                    const __half* src = (pl ? rrl : rrh) + (size_t)r * H2 + k0 + sg * 8;
                    cpa16(dst, src);
                }
            }
            cpa16(wdst0 + st * WSTB, wsrc + wgoff + k0);
        };

        issue(0, 0); cpa_commit();
        issue(1, 32); cpa_commit();
        issue(2, 64); cpa_commit();

        for (int ch = 0; ch < H2 / 32; ch++) {
            cpa_wait2();
            __syncthreads();
            const int st = ch & 3;
            const unsigned bH = st * HSTB, bW = st * WSTB;
#pragma unroll
            for (int kk16 = 0; kk16 < 2; kk16++) {
                const int kc2 = kk16 * 32;
                unsigned ah[2][4], al[2][4], bh[2], bl[2];
                const unsigned aoff = (unsigned)((mh + lr + lbit8 * 8) * 80 + kc2 + lbit16 * 16);
                const unsigned boff = (unsigned)((g * 16 + nh + lbr) * 80 + kc2 + lbk * 16);
                ldsm2(bh, sWh + bW + boff);
                ldsm2(bl, sWl + bW + boff);
#pragma unroll
                for (int mt = 0; mt < 2; mt++) {
                    ldsm4(ah[mt], sHh + bH + aoff + mt * 16 * 80);
                    ldsm4(al[mt], sHl + bH + aoff + mt * 16 * 80);
                }
#pragma unroll
                for (int mt = 0; mt < 2; mt++) {
                    mma16816(chi[mt], ah[mt], bh);
                    mma16816(clo[mt], ah[mt], bl);
                    mma16816(clo[mt], al[mt], bh);
                }
            }
            if (ch + 3 < H2 / 32) issue((ch + 3) & 3, (ch + 3) * 32);
            cpa_commit();
        }
    }

#pragma unroll
    for (int mt = 0; mt < 2; mt++) {
        int rm = mh + mt * 16 + g4, cn = nh + 2 * t4;
        gh[(g * 64 + rm) * 16 + cn]           = chi[mt][0] + clo[mt][0] * LO_INV;
        gh[(g * 64 + rm) * 16 + cn + 1]       = chi[mt][1] + clo[mt][1] * LO_INV;
        gh[(g * 64 + rm + 8) * 16 + cn]       = chi[mt][2] + clo[mt][2] * LO_INV;
        gh[(g * 64 + rm + 8) * 16 + cn + 1]   = chi[mt][3] + clo[mt][3] * LO_INV;
    }
    __syncthreads();

    for (int o = tid; o < 1024; o += 384) {
        int mm = o >> 4, jj = o & 15, j = j0 + jj;
        float r = sigmoidf_(bih[j]          + gh[(0 * 64 + mm) * 16 + jj] + bhh[j]);
        float z = sigmoidf_(bih[H2 + j]     + gh[(1 * 64 + mm) * 16 + jj] + bhh[H2 + j]);
        float n = tanhf    (bih[2 * H2 + j] + r * (gh[(2 * 64 + mm) * 16 + jj] + bhh[2 * H2 + j]));
        float hp = __half2float(rrh[(size_t)mm * H2 + j]) + __half2float(rrl[(size_t)mm * H2 + j]) * LO_INV;
        float hv = (1.0f - z) * n + z * hp;
        __half phi, plo; splitf(hv, phi, plo);
        size_t oi = ((size_t)(mm * T + t)) * H2 + j;
        g_yhd[oi] = phi; g_yld[oi] = plo;
        rwh[(size_t)mm * H2 + j] = phi; rwl[(size_t)mm * H2 + j] = plo;
    }
}

// ---------------- gather enc_hidden; seed decoder ring buf0 ----------------
__global__ void gather_kernel(const __half* __restrict__ yh, const __half* __restrict__ yl,
                              const int* __restrict__ seq_len,
                              float* __restrict__ out_hid)
{
    int idx = blockIdx.x * 256 + threadIdx.x;   // B*H2
    int b = idx >> 11, k = idx & (H2 - 1);
    int sl = seq_len[b];
    sl = sl < 1 ? 1 : (sl > T ? T : sl);
    size_t src = ((size_t)(b * T + sl - 1)) * H2 + k;
    __half h = yh[src], l = yl[src];
    out_hid[idx] = __half2float(h) + __half2float(l) * LO_INV;
    g_dhrh[(size_t)b * H2 + k] = h;
    g_dhrl[(size_t)b * H2 + k] = l;
}

// ---------------- host launcher ----------------
extern "C" void kernel_launch(void* const* d_in, const int* in_sizes, int n_in,
                              void* d_out, int out_size)
{
    const float* x    = (const float*)d_in[0];
    const int*   slen = (const int*)  d_in[1];
    const float* Wih0 = (const float*)d_in[2];
    const float* Whh0 = (const float*)d_in[3];
    const float* b0   = (const float*)d_in[4];
    const float* Wih  = (const float*)d_in[5];
    const float* Whh  = (const float*)d_in[6];
    const float* bb   = (const float*)d_in[7];
    const float* dWhh = (const float*)d_in[9];
    const float* db   = (const float*)d_in[10];
    const float* oW   = (const float*)d_in[11];
    const float* ob   = (const float*)d_in[12];
    float* out = (float*)d_out;

    // idempotent, non-stream, capture-safe; called every invocation (no static guards)
    cudaFuncSetAttribute(enc_step_h5, cudaFuncAttributeMaxDynamicSharedMemorySize, SMEM_STEP);
    cudaFuncSetAttribute(dec_step_h5, cudaFuncAttributeMaxDynamicSharedMemorySize, SMEM_STEP);

    float *p_xg;
    __half *p_yha, *p_yla, *p_yhb, *p_ylb, *p_yhd, *p_yld, *p_xh, *p_xl;
    __half *p_W0h, *p_W0l, *p_Wh, *p_Wl, *p_dWh, *p_dWl, *p_Wih_h, *p_Wih_l,
           *p_Wi0h, *p_Wi0l, *p_oWh, *p_oWl;
    cudaGetSymbolAddress((void**)&p_xg, g_xg);
    cudaGetSymbolAddress((void**)&p_yha, g_yha);
    cudaGetSymbolAddress((void**)&p_yla, g_yla);
    cudaGetSymbolAddress((void**)&p_yhb, g_yhb);
    cudaGetSymbolAddress((void**)&p_ylb, g_ylb);
    cudaGetSymbolAddress((void**)&p_yhd, g_yhd);
    cudaGetSymbolAddress((void**)&p_yld, g_yld);
    cudaGetSymbolAddress((void**)&p_xh, g_xh);
    cudaGetSymbolAddress((void**)&p_xl, g_xl);
    cudaGetSymbolAddress((void**)&p_W0h, s_Whh0h);
    cudaGetSymbolAddress((void**)&p_W0l, s_Whh0l);
    cudaGetSymbolAddress((void**)&p_Wh, s_Whhh);
    cudaGetSymbolAddress((void**)&p_Wl, s_Whhl);
    cudaGetSymbolAddress((void**)&p_dWh, s_dWh);
    cudaGetSymbolAddress((void**)&p_dWl, s_dWl);
    cudaGetSymbolAddress((void**)&p_Wih_h, s_Wihh);
    cudaGetSymbolAddress((void**)&p_Wih_l, s_Wihl);
    cudaGetSymbolAddress((void**)&p_Wi0h, s_Wih0h);
    cudaGetSymbolAddress((void**)&p_Wi0l, s_Wih0l);
    cudaGetSymbolAddress((void**)&p_oWh, s_oWh);
    cudaGetSymbolAddress((void**)&p_oWl, s_oWl);

    // ---- prep: pre-split weights / x ----
    k_split<<<2048, 256>>>(Whh0, p_W0h, p_W0l, 2 * G3 * H);
    k_split<<<2048, 256>>>(Whh,  p_Wh,  p_Wl,  4 * G3 * H);
    k_split<<<2048, 256>>>(dWhh, p_dWh, p_dWl, G6 * H2);
    k_split<<<4096, 256>>>(Wih,  p_Wih_h, p_Wih_l, 4 * G3 * H2);
    k_split<<<512,  256>>>(oW,   p_oWh, p_oWl, D * H2);
    k_split_pad<<<512, 256>>>(Wih0, p_Wi0h, p_Wi0l, 2 * G3, D, DP);
    k_split_pad<<<512, 256>>>(x, p_xh, p_xl, BT, D, DP);

    const dim3 gG(G3 / 64, BT / 128);
    const dim3 gE(H / 16, 2);
    const int  gDc = H2 / 16;

    // ---- encoder layer 0 (K = 80 padded) ----
    gemm_h2p<<<gG, 256>>>(p_xh, p_xl, DP, p_Wi0h,                 p_Wi0l,                 b0,        p_xg,      BT, G3, DP, G6);
    gemm_h2p<<<gG, 256>>>(p_xh, p_xl, DP, p_Wi0h + (size_t)G3*DP, p_Wi0l + (size_t)G3*DP, b0 + 2*G3, p_xg + G3, BT, G3, DP, G6);
    for (int t = 0; t < T; t++)
        enc_step_h5<<<gE, 384, SMEM_STEP>>>(p_W0h, p_W0l, b0 + G3, 2 * G3, p_yha, p_yla, t);

    // ---- encoder layer 1 ----
    gemm_h2p<<<gG, 256>>>(p_yha, p_yla, H2, p_Wih_h,                 p_Wih_l,                 bb,        p_xg,      BT, G3, H2, G6);
    gemm_h2p<<<gG, 256>>>(p_yha, p_yla, H2, p_Wih_h + (size_t)G3*H2, p_Wih_l + (size_t)G3*H2, bb + 2*G3, p_xg + G3, BT, G3, H2, G6);
    for (int t = 0; t < T; t++)
        enc_step_h5<<<gE, 384, SMEM_STEP>>>(p_Wh, p_Wl, bb + G3, 2 * G3, p_yhb, p_ylb, t);

    // ---- encoder layer 2 ----
    gemm_h2p<<<gG, 256>>>(p_yhb, p_ylb, H2, p_Wih_h + (size_t)2*G3*H2, p_Wih_l + (size_t)2*G3*H2, bb + 4*G3, p_xg,      BT, G3, H2, G6);
    gemm_h2p<<<gG, 256>>>(p_yhb, p_ylb, H2, p_Wih_h + (size_t)3*G3*H2, p_Wih_l + (size_t)3*G3*H2, bb + 6*G3, p_xg + G3, BT, G3, H2, G6);
    for (int t = 0; t < T; t++)
        enc_step_h5<<<gE, 384, SMEM_STEP>>>(p_Wh + (size_t)2*G3*H, p_Wl + (size_t)2*G3*H, bb + 5*G3, 2 * G3, p_yha, p_yla, t);

    // ---- gather (enc_hidden out + decoder ring seed) ----
    gather_kernel<<<(B * H2) / 256, 256>>>(p_yha, p_yla, slen, out);

    // ---- decoder scan ----
    for (int t = 0; t < T; t++)
        dec_step_h5<<<gDc, 384, SMEM_STEP>>>(db, db + G6, t);

    // ---- output projection ----
    gemm_h2p<<<dim3(2, BT / 128), 256>>>(p_yhd, p_yld, H2, p_oWh, p_oWl, ob,
                                         out + (size_t)B * H2, BT, D, H2, D);
}

// round 16
// speedup vs baseline: 2.5777x; 1.0092x over previous
#include <cuda_runtime.h>
#include <cuda_fp16.h>
#include <math.h>

// Problem dims
#define B   64
#define T   100
#define D   75
#define DP  80      // padded K for layer-0 / x
#define H   1024
#define H2  2048
#define G3  3072
#define G6  6144
#define BT  6400

#define LO_SCALE 4096.0f
#define LO_INV   (1.0f/4096.0f)

// ---------------- scratch (device globals; no allocation) ----------------
__device__ float  g_xg[(size_t)BT * G6];           // input gates (fp32)
__device__ __half g_yha[(size_t)BT * H2], g_yla[(size_t)BT * H2];
__device__ __half g_yhb[(size_t)BT * H2], g_ylb[(size_t)BT * H2];
__device__ __half g_yhd[(size_t)BT * H2], g_yld[(size_t)BT * H2];
__device__ __half g_xh[(size_t)BT * DP],  g_xl[(size_t)BT * DP];
__device__ __half g_ehrh[(size_t)2*2*B*H],  g_ehrl[(size_t)2*2*B*H];   // enc ring
__device__ __half g_dhrh[(size_t)2*B*H2],   g_dhrl[(size_t)2*B*H2];    // dec ring
// pre-split weight planes
__device__ __half s_Whh0h[(size_t)2*G3*H],  s_Whh0l[(size_t)2*G3*H];
__device__ __half s_Whhh [(size_t)4*G3*H],  s_Whhl [(size_t)4*G3*H];
__device__ __half s_dWh  [(size_t)G6*H2],   s_dWl  [(size_t)G6*H2];
__device__ __half s_Wihh [(size_t)4*G3*H2], s_Wihl [(size_t)4*G3*H2];
__device__ __half s_Wih0h[(size_t)2*G3*DP], s_Wih0l[(size_t)2*G3*DP];
__device__ __half s_oWh  [(size_t)D*H2],    s_oWl  [(size_t)D*H2];

__device__ __forceinline__ float sigmoidf_(float x) { return 1.0f / (1.0f + __expf(-x)); }

__device__ __forceinline__ void splitf(float v, __half& hi, __half& lo) {
    hi = __float2half_rn(v);
    lo = __float2half_rn((v - __half2float(hi)) * LO_SCALE);
}

__device__ __forceinline__ void mma16816(float* c, const unsigned* a, const unsigned* b) {
    asm volatile(
        "mma.sync.aligned.m16n8k16.row.col.f32.f16.f16.f32 "
        "{%0,%1,%2,%3},{%4,%5,%6,%7},{%8,%9},{%0,%1,%2,%3};\n"
        : "+f"(c[0]), "+f"(c[1]), "+f"(c[2]), "+f"(c[3])
        : "r"(a[0]), "r"(a[1]), "r"(a[2]), "r"(a[3]), "r"(b[0]), "r"(b[1]));
}
__device__ __forceinline__ void ldsm4(unsigned* a, unsigned addr) {
    asm volatile("ldmatrix.sync.aligned.m8n8.x4.shared.b16 {%0,%1,%2,%3}, [%4];"
        : "=r"(a[0]), "=r"(a[1]), "=r"(a[2]), "=r"(a[3]) : "r"(addr));
}
__device__ __forceinline__ void ldsm2(unsigned* b, unsigned addr) {
    asm volatile("ldmatrix.sync.aligned.m8n8.x2.shared.b16 {%0,%1}, [%2];"
        : "=r"(b[0]), "=r"(b[1]) : "r"(addr));
}
__device__ __forceinline__ unsigned smaddr(const void* p) {
    return (unsigned)__cvta_generic_to_shared(p);
}
__device__ __forceinline__ void cpa16(unsigned dst, const void* src) {
    asm volatile("cp.async.cg.shared.global [%0], [%1], 16;" :: "r"(dst), "l"(src));
}
__device__ __forceinline__ void cpa_commit() {
    asm volatile("cp.async.commit_group;" ::: "memory");
}
__device__ __forceinline__ void cpa_wait2() {
    asm volatile("cp.async.wait_group 2;" ::: "memory");
}

// ================= merged prep kernel (ONE launch) =================
// Vector jobs (8 fp32 -> 8+8 halves): A Whh0, B Whh, C dWhh, D Wih, E oW
// Scalar padded jobs: F Wih0 (rows 2*G3, 75->80), G x (rows BT, 75->80)
#define UA ((size_t)2*G3*H/8)
#define UB ((size_t)4*G3*H/8)
#define UC ((size_t)G6*H2/8)
#define UD ((size_t)4*G3*H2/8)
#define UE ((size_t)D*H2/8)
#define UF ((size_t)2*G3*DP)
#define UG ((size_t)BT*DP)
__global__ void k_prep(const float* __restrict__ Whh0, const float* __restrict__ Whh,
                       const float* __restrict__ dWhh, const float* __restrict__ Wih,
                       const float* __restrict__ oW,   const float* __restrict__ Wih0,
                       const float* __restrict__ x)
{
    const size_t nA = UA, nB = nA + UB, nC = nB + UC, nD = nC + UD, nE = nD + UE;
    const size_t nF = nE + UF, nG = nF + UG;
    for (size_t u = blockIdx.x * (size_t)blockDim.x + threadIdx.x; u < nG;
         u += (size_t)gridDim.x * blockDim.x) {
        if (u < nE) {
            const float* src; __half *hi, *lo; size_t off;
            if      (u < nA) { src = Whh0; hi = s_Whh0h; lo = s_Whh0l; off = u; }
            else if (u < nB) { src = Whh;  hi = s_Whhh;  lo = s_Whhl;  off = u - nA; }
            else if (u < nC) { src = dWhh; hi = s_dWh;   lo = s_dWl;   off = u - nB; }
            else if (u < nD) { src = Wih;  hi = s_Wihh;  lo = s_Wihl;  off = u - nC; }
            else             { src = oW;   hi = s_oWh;   lo = s_oWl;   off = u - nD; }
            size_t e = off * 8;
            float4 v0 = *(const float4*)&src[e];
            float4 v1 = *(const float4*)&src[e + 4];
            __half h[8], l[8];
            splitf(v0.x, h[0], l[0]); splitf(v0.y, h[1], l[1]);
            splitf(v0.z, h[2], l[2]); splitf(v0.w, h[3], l[3]);
            splitf(v1.x, h[4], l[4]); splitf(v1.y, h[5], l[5]);
            splitf(v1.z, h[6], l[6]); splitf(v1.w, h[7], l[7]);
            *(uint4*)&hi[e] = *(uint4*)h;
            *(uint4*)&lo[e] = *(uint4*)l;
        } else if (u < nF) {
            size_t i = u - nE;                 // Wih0 pad-split, scalar
            int r = (int)(i / DP), k = (int)(i - (size_t)r * DP);
            float v = (k < D) ? Wih0[(size_t)r * D + k] : 0.0f;
            __half h, l; splitf(v, h, l);
            s_Wih0h[i] = h; s_Wih0l[i] = l;
        } else {
            size_t i = u - nF;                 // x pad-split, scalar
            int r = (int)(i / DP), k = (int)(i - (size_t)r * DP);
            float v = (k < D) ? x[(size_t)r * D + k] : 0.0f;
            __half h, l; splitf(v, h, l);
            g_xh[i] = h; g_xl[i] = l;
        }
    }
}

// ================= GEMM: dual-plane A x pre-split W (ldmatrix) =================
__global__ __launch_bounds__(256) void gemm_h2p(
    const __half* __restrict__ Ahi, const __half* __restrict__ Alo, int lda,
    const __half* __restrict__ Whi, const __half* __restrict__ Wlo,
    const float* __restrict__ bias, float* __restrict__ C,
    int M, int N, int K, int ldc)
{
    __shared__ __half Ah[128][40], Al[128][40];
    __shared__ __half Bh[64][40],  Bl[64][40];

    const int tid = threadIdx.x;
    const int w = tid >> 5, lane = tid & 31;
    const int g4 = lane >> 2, t4 = lane & 3;
    const int m0 = blockIdx.y * 128, n0 = blockIdx.x * 64;
    const int wm = (w >> 1) * 32, wn = (w & 1) * 32;

    const int ar[2]  = {(0*256+tid)>>2, (1*256+tid)>>2};
    const int asg[2] = {(0*256+tid)&3,  (1*256+tid)&3};
    const int bidx[2] = {0*256+tid, 1*256+tid};

    const int lr = lane & 7, lbit8 = (lane >> 3) & 1, lbit16 = (lane >> 4) & 1;
    const int lb = lane & 15, lbr = lb & 7, lbk = (lb >> 3) & 1;
    const unsigned sAh = smaddr(&Ah[0][0]), sAl = smaddr(&Al[0][0]);
    const unsigned sBh = smaddr(&Bh[0][0]), sBl = smaddr(&Bl[0][0]);

    float chi[2][4][4] = {}, clo[2][4][4] = {};
    const int nch = (K + 31) / 32;

    uint4 pah[2], pal[2], pb[2];
    const uint4 z4 = make_uint4(0, 0, 0, 0);

    auto loadA = [&](int k0) {
#pragma unroll
        for (int i = 0; i < 2; i++) {
            int gm = m0 + ar[i], gk = k0 + asg[i] * 8;
            bool ok = (gm < M) && (gk < K);
            pah[i] = ok ? *(const uint4*)&Ahi[(size_t)gm * lda + gk] : z4;
            pal[i] = ok ? *(const uint4*)&Alo[(size_t)gm * lda + gk] : z4;
        }
    };
    auto loadB = [&](int k0) {
#pragma unroll
        for (int i = 0; i < 2; i++) {
            int idx = bidx[i], pl = idx >> 8, wi = idx & 255;
            int gn = n0 + (wi >> 2), gk = k0 + (wi & 3) * 8;
            bool ok = (gn < N) && (gk < K);
            const __half* src = pl ? Wlo : Whi;
            pb[i] = ok ? *(const uint4*)&src[(size_t)gn * K + gk] : z4;
        }
    };
    auto storeAB = [&]() {
#pragma unroll
        for (int i = 0; i < 2; i++) {
            *(uint4*)&Ah[ar[i]][asg[i] * 8] = pah[i];
            *(uint4*)&Al[ar[i]][asg[i] * 8] = pal[i];
        }
#pragma unroll
        for (int i = 0; i < 2; i++) {
            int idx = bidx[i], pl = idx >> 8, wi = idx & 255;
            if (pl) *(uint4*)&Bl[wi >> 2][(wi & 3) * 8] = pb[i];
            else    *(uint4*)&Bh[wi >> 2][(wi & 3) * 8] = pb[i];
        }
    };

    loadA(0); loadB(0);
    for (int ch = 0; ch < nch; ch++) {
        storeAB();
        __syncthreads();
        if (ch + 1 < nch) { loadA((ch + 1) * 32); loadB((ch + 1) * 32); }

#pragma unroll
        for (int kk16 = 0; kk16 < 2; kk16++) {
            const int kc2 = kk16 * 32;
            unsigned ah[2][4], al[2][4], bh[4][2], bl[4][2];
            const unsigned aoff = (unsigned)((wm + lr + lbit8 * 8) * 80 + kc2 + lbit16 * 16);
            const unsigned boff0 = (unsigned)((wn + lbr) * 80 + kc2 + lbk * 16);
#pragma unroll
            for (int mt = 0; mt < 2; mt++) {
                ldsm4(ah[mt], sAh + aoff + mt * 16 * 80);
                ldsm4(al[mt], sAl + aoff + mt * 16 * 80);
            }
#pragma unroll
            for (int nt = 0; nt < 4; nt++) {
                ldsm2(bh[nt], sBh + boff0 + nt * 8 * 80);
                ldsm2(bl[nt], sBl + boff0 + nt * 8 * 80);
            }
#pragma unroll
            for (int mt = 0; mt < 2; mt++)
#pragma unroll
                for (int nt = 0; nt < 4; nt++) {
                    mma16816(chi[mt][nt], ah[mt], bh[nt]);
                    mma16816(clo[mt][nt], ah[mt], bl[nt]);
                    mma16816(clo[mt][nt], al[mt], bh[nt]);
                }
        }
        __syncthreads();
    }

#pragma unroll
    for (int mt = 0; mt < 2; mt++)
#pragma unroll
        for (int nt = 0; nt < 4; nt++) {
            int rm = m0 + wm + mt * 16 + g4;
            int cn = n0 + wn + nt * 8 + 2 * t4;
            const float* ch_ = chi[mt][nt];
            const float* cl_ = clo[mt][nt];
            if (rm < M) {
                if (cn < N)     C[(size_t)rm * ldc + cn]     = ch_[0] + cl_[0] * LO_INV + bias[cn];
                if (cn + 1 < N) C[(size_t)rm * ldc + cn + 1] = ch_[1] + cl_[1] * LO_INV + bias[cn + 1];
            }
            if (rm + 8 < M) {
                if (cn < N)     C[(size_t)(rm + 8) * ldc + cn]     = ch_[2] + cl_[2] * LO_INV + bias[cn];
                if (cn + 1 < N) C[(size_t)(rm + 8) * ldc + cn + 1] = ch_[3] + cl_[3] * LO_INV + bias[cn + 1];
            }
        }
}

// ======= step-kernel shared constants (dynamic smem, 4-stage cp.async ring) =======
#define HPL (64 * 40)
#define WPL (48 * 40)
#define HSTB (HPL * 2)
#define WSTB (WPL * 2)
#define SMEM_STEP (4 * (2*HSTB + 2*WSTB) + 3 * 64 * 16 * 4)   // 83968

// ================= encoder GRU step =================
__global__ __launch_bounds__(384) void enc_step_h5(
    const __half* __restrict__ Whi_all, const __half* __restrict__ Wlo_all,
    const float* __restrict__ bhh_base, int bhh_stride,
    __half* __restrict__ yh, __half* __restrict__ yl, int t)
{
    extern __shared__ char dsm[];
    __half* Hh = (__half*)dsm;
    __half* Hl = Hh + 4 * HPL;
    __half* Wh = Hl + 4 * HPL;
    __half* Wl = Wh + 4 * WPL;
    float*  gh = (float*)(Wl + 4 * WPL);

    const int dir = blockIdx.y;
    const int j0  = blockIdx.x * 16;
    const __half* Whi = Whi_all + (size_t)dir * G3 * H;
    const __half* Wlo = Wlo_all + (size_t)dir * G3 * H;
    const float* bhh = bhh_base + (size_t)dir * bhh_stride;
    const __half* rrh = g_ehrh + ((size_t)((t & 1) * 2 + dir)) * B * H;
    const __half* rrl = g_ehrl + ((size_t)((t & 1) * 2 + dir)) * B * H;
    __half* rwh = g_ehrh + ((size_t)(((t + 1) & 1) * 2 + dir)) * B * H;
    __half* rwl = g_ehrl + ((size_t)(((t + 1) & 1) * 2 + dir)) * B * H;

    const int tid = threadIdx.x;
    const int w = tid >> 5, lane = tid & 31;
    const int g = w >> 2, mh = ((w >> 1) & 1) * 32, nh = (w & 1) * 8;
    const int g4 = lane >> 2, t4 = lane & 3;

    const int lr = lane & 7, lbit8 = (lane >> 3) & 1, lbit16 = (lane >> 4) & 1;
    const int lb = lane & 15, lbr = lb & 7, lbk = (lb >> 3) & 1;
    const unsigned sHh = smaddr(Hh), sHl = smaddr(Hl);
    const unsigned sWh = smaddr(Wh), sWl = smaddr(Wl);

    float chi[2][4] = {}, clo[2][4] = {};

    if (t > 0) {
        const int wpl = tid >= 192;
        const int widx = wpl ? tid - 192 : tid;
        const int wr = widx >> 2, wsg = widx & 3;
        const int wgate = wr >> 4, wjj = wr & 15;
        const size_t wgoff = ((size_t)(wgate * H + j0 + wjj)) * H + wsg * 8;
        const __half* wsrc = wpl ? Wlo : Whi;
        const unsigned wdst0 = (wpl ? sWl : sWh) + (unsigned)(wr * 80 + wsg * 16);

        auto issue = [&](int st, int k0) {
#pragma unroll
            for (int i = 0; i < 2; i++) {
                int s = tid + i * 384;
                if (s < 512) {
                    int pl = s >> 8, r = (s & 255) >> 2, sg = s & 3;
                    unsigned dst = (pl ? sHl : sHh) + (unsigned)(st * HSTB + r * 80 + sg * 16);
                    const __half* src = (pl ? rrl : rrh) + (size_t)r * H + k0 + sg * 8;
                    cpa16(dst, src);
                }
            }
            cpa16(wdst0 + st * WSTB, wsrc + wgoff + k0);
        };

        issue(0, 0); cpa_commit();
        issue(1, 32); cpa_commit();
        issue(2, 64); cpa_commit();

        for (int ch = 0; ch < H / 32; ch++) {
            cpa_wait2();
            __syncthreads();
            const int st = ch & 3;
            const unsigned bH = st * HSTB, bW = st * WSTB;
#pragma unroll
            for (int kk16 = 0; kk16 < 2; kk16++) {
                const int kc2 = kk16 * 32;
                unsigned ah[2][4], al[2][4], bh[2], bl[2];
                const unsigned aoff = (unsigned)((mh + lr + lbit8 * 8) * 80 + kc2 + lbit16 * 16);
                const unsigned boff = (unsigned)((g * 16 + nh + lbr) * 80 + kc2 + lbk * 16);
                ldsm2(bh, sWh + bW + boff);
                ldsm2(bl, sWl + bW + boff);
#pragma unroll
                for (int mt = 0; mt < 2; mt++) {
                    ldsm4(ah[mt], sHh + bH + aoff + mt * 16 * 80);
                    ldsm4(al[mt], sHl + bH + aoff + mt * 16 * 80);
                }
#pragma unroll
                for (int mt = 0; mt < 2; mt++) {
                    mma16816(chi[mt], ah[mt], bh);
                    mma16816(clo[mt], ah[mt], bl);
                    mma16816(clo[mt], al[mt], bh);
                }
            }
            if (ch + 3 < H / 32) issue((ch + 3) & 3, (ch + 3) * 32);
            cpa_commit();
        }
    }

#pragma unroll
    for (int mt = 0; mt < 2; mt++) {
        int rm = mh + mt * 16 + g4, cn = nh + 2 * t4;
        gh[(g * 64 + rm) * 16 + cn]           = chi[mt][0] + clo[mt][0] * LO_INV;
        gh[(g * 64 + rm) * 16 + cn + 1]       = chi[mt][1] + clo[mt][1] * LO_INV;
        gh[(g * 64 + rm + 8) * 16 + cn]       = chi[mt][2] + clo[mt][2] * LO_INV;
        gh[(g * 64 + rm + 8) * 16 + cn + 1]   = chi[mt][3] + clo[mt][3] * LO_INV;
    }
    __syncthreads();

    for (int o = tid; o < 1024; o += 384) {
        int mm = o >> 4, jj = o & 15, j = j0 + jj;
        const float* xgp = g_xg + (size_t)(mm * T + t) * G6 + dir * G3;
        float r = sigmoidf_(xgp[j]         + gh[(0 * 64 + mm) * 16 + jj] + bhh[j]);
        float z = sigmoidf_(xgp[H + j]     + gh[(1 * 64 + mm) * 16 + jj] + bhh[H + j]);
        float n = tanhf    (xgp[2 * H + j] + r * (gh[(2 * 64 + mm) * 16 + jj] + bhh[2 * H + j]));
        float hp = (t == 0) ? 0.0f
                 : __half2float(rrh[(size_t)mm * H + j]) + __half2float(rrl[(size_t)mm * H + j]) * LO_INV;
        float hv = (1.0f - z) * n + z * hp;
        __half phi, plo; splitf(hv, phi, plo);
        size_t oi = ((size_t)(mm * T + t)) * H2 + dir * H + j;
        yh[oi] = phi; yl[oi] = plo;
        rwh[(size_t)mm * H + j] = phi; rwl[(size_t)mm * H + j] = plo;
    }
}

// ================= decoder GRU step =================
__global__ __launch_bounds__(384) void dec_step_h5(
    const float* __restrict__ bih, const float* __restrict__ bhh, int t)
{
    extern __shared__ char dsm[];
    __half* Hh = (__half*)dsm;
    __half* Hl = Hh + 4 * HPL;
    __half* Wh = Hl + 4 * HPL;
    __half* Wl = Wh + 4 * WPL;
    float*  gh = (float*)(Wl + 4 * WPL);

    const int j0 = blockIdx.x * 16;
    const __half* rrh = g_dhrh + ((size_t)(t & 1)) * B * H2;
    const __half* rrl = g_dhrl + ((size_t)(t & 1)) * B * H2;
    __half* rwh = g_dhrh + ((size_t)((t + 1) & 1)) * B * H2;
    __half* rwl = g_dhrl + ((size_t)((t + 1) & 1)) * B * H2;

    const int tid = threadIdx.x;
    const int w = tid >> 5, lane = tid & 31;
    const int g = w >> 2, mh = ((w >> 1) & 1) * 32, nh = (w & 1) * 8;
    const int g4 = lane >> 2, t4 = lane & 3;

    const int lr = lane & 7, lbit8 = (lane >> 3) & 1, lbit16 = (lane >> 4) & 1;
    const int lb = lane & 15, lbr = lb & 7, lbk = (lb >> 3) & 1;
    const unsigned sHh = smaddr(Hh), sHl = smaddr(Hl);
    const unsigned sWh = smaddr(Wh), sWl = smaddr(Wl);

    float chi[2][4] = {}, clo[2][4] = {};

    {
        const int wpl = tid >= 192;
        const int widx = wpl ? tid - 192 : tid;
        const int wr = widx >> 2, wsg = widx & 3;
        const int wgate = wr >> 4, wjj = wr & 15;
        const size_t wgoff = ((size_t)(wgate * H2 + j0 + wjj)) * H2 + wsg * 8;
        const __half* wsrc = wpl ? s_dWl : s_dWh;
        const unsigned wdst0 = (wpl ? sWl : sWh) + (unsigned)(wr * 80 + wsg * 16);

        auto issue = [&](int st, int k0) {
#pragma unroll
            for (int i = 0; i < 2; i++) {
                int s = tid + i * 384;
                if (s < 512) {
                    int pl = s >> 8, r = (s & 255) >> 2, sg = s & 3;
                    unsigned dst = (pl ? sHl : sHh) + (unsigned)(st * HSTB + r * 80 + sg * 16);
                    const __half* src = (pl ? rrl : rrh) + (size_t)r * H2 + k0 + sg * 8;
                    cpa16(dst, src);
                }
            }
            cpa16(wdst0 + st * WSTB, wsrc + wgoff + k0);
        };

        issue(0, 0); cpa_commit();
        issue(1, 32); cpa_commit();
        issue(2, 64); cpa_commit();

        for (int ch = 0; ch < H2 / 32; ch++) {
            cpa_wait2();
            __syncthreads();
            const int st = ch & 3;
            const unsigned bH = st * HSTB, bW = st * WSTB;
#pragma unroll
            for (int kk16 = 0; kk16 < 2; kk16++) {
                const int kc2 = kk16 * 32;
                unsigned ah[2][4], al[2][4], bh[2], bl[2];
                const unsigned aoff = (unsigned)((mh + lr + lbit8 * 8) * 80 + kc2 + lbit16 * 16);
                const unsigned boff = (unsigned)((g * 16 + nh + lbr) * 80 + kc2 + lbk * 16);
                ldsm2(bh, sWh + bW + boff);
                ldsm2(bl, sWl + bW + boff);
#pragma unroll
                for (int mt = 0; mt < 2; mt++) {
                    ldsm4(ah[mt], sHh + bH + aoff + mt * 16 * 80);
                    ldsm4(al[mt], sHl + bH + aoff + mt * 16 * 80);
                }
#pragma unroll
                for (int mt = 0; mt < 2; mt++) {
                    mma16816(chi[mt], ah[mt], bh);
                    mma16816(clo[mt], ah[mt], bl);
                    mma16816(clo[mt], al[mt], bh);
                }
            }
            if (ch + 3 < H2 / 32) issue((ch + 3) & 3, (ch + 3) * 32);
            cpa_commit();
        }
    }

#pragma unroll
    for (int mt = 0; mt < 2; mt++) {
        int rm = mh + mt * 16 + g4, cn = nh + 2 * t4;
        gh[(g * 64 + rm) * 16 + cn]           = chi[mt][0] + clo[mt][0] * LO_INV;
        gh[(g * 64 + rm) * 16 + cn + 1]       = chi[mt][1] + clo[mt][1] * LO_INV;
        gh[(g * 64 + rm + 8) * 16 + cn]       = chi[mt][2] + clo[mt][2] * LO_INV;
        gh[(g * 64 + rm + 8) * 16 + cn + 1]   = chi[mt][3] + clo[mt][3] * LO_INV;
    }
    __syncthreads();

    for (int o = tid; o < 1024; o += 384) {
        int mm = o >> 4, jj = o & 15, j = j0 + jj;
        float r = sigmoidf_(bih[j]          + gh[(0 * 64 + mm) * 16 + jj] + bhh[j]);
        float z = sigmoidf_(bih[H2 + j]     + gh[(1 * 64 + mm) * 16 + jj] + bhh[H2 + j]);
        float n = tanhf    (bih[2 * H2 + j] + r * (gh[(2 * 64 + mm) * 16 + jj] + bhh[2 * H2 + j]));
        float hp = __half2float(rrh[(size_t)mm * H2 + j]) + __half2float(rrl[(size_t)mm * H2 + j]) * LO_INV;
        float hv = (1.0f - z) * n + z * hp;
        __half phi, plo; splitf(hv, phi, plo);
        size_t oi = ((size_t)(mm * T + t)) * H2 + j;
        g_yhd[oi] = phi; g_yld[oi] = plo;
        rwh[(size_t)mm * H2 + j] = phi; rwl[(size_t)mm * H2 + j] = plo;
    }
}

// ---------------- gather enc_hidden; seed decoder ring buf0 ----------------
__global__ void gather_kernel(const __half* __restrict__ yh, const __half* __restrict__ yl,
                              const int* __restrict__ seq_len,
                              float* __restrict__ out_hid)
{
    int idx = blockIdx.x * 256 + threadIdx.x;   // B*H2
    int b = idx >> 11, k = idx & (H2 - 1);
    int sl = seq_len[b];
    sl = sl < 1 ? 1 : (sl > T ? T : sl);
    size_t src = ((size_t)(b * T + sl - 1)) * H2 + k;
    __half h = yh[src], l = yl[src];
    out_hid[idx] = __half2float(h) + __half2float(l) * LO_INV;
    g_dhrh[(size_t)b * H2 + k] = h;
    g_dhrl[(size_t)b * H2 + k] = l;
}

// ---------------- host launcher ----------------
extern "C" void kernel_launch(void* const* d_in, const int* in_sizes, int n_in,
                              void* d_out, int out_size)
{
    const float* x    = (const float*)d_in[0];
    const int*   slen = (const int*)  d_in[1];
    const float* Wih0 = (const float*)d_in[2];
    const float* Whh0 = (const float*)d_in[3];
    const float* b0   = (const float*)d_in[4];
    const float* Wih  = (const float*)d_in[5];
    const float* Whh  = (const float*)d_in[6];
    const float* bb   = (const float*)d_in[7];
    const float* dWhh = (const float*)d_in[9];
    const float* db   = (const float*)d_in[10];
    const float* oW   = (const float*)d_in[11];
    const float* ob   = (const float*)d_in[12];
    float* out = (float*)d_out;

    // idempotent, non-stream, capture-safe; no static guards
    cudaFuncSetAttribute(enc_step_h5, cudaFuncAttributeMaxDynamicSharedMemorySize, SMEM_STEP);
    cudaFuncSetAttribute(dec_step_h5, cudaFuncAttributeMaxDynamicSharedMemorySize, SMEM_STEP);

    __half *p_yha, *p_yla, *p_yhb, *p_ylb, *p_yhd, *p_yld, *p_xh, *p_xl;
    float *p_xg;
    __half *p_W0h, *p_W0l, *p_Wh, *p_Wl, *p_Wih_h, *p_Wih_l, *p_Wi0h, *p_Wi0l, *p_oWh, *p_oWl;
    cudaGetSymbolAddress((void**)&p_xg, g_xg);
    cudaGetSymbolAddress((void**)&p_yha, g_yha);
    cudaGetSymbolAddress((void**)&p_yla, g_yla);
    cudaGetSymbolAddress((void**)&p_yhb, g_yhb);
    cudaGetSymbolAddress((void**)&p_ylb, g_ylb);
    cudaGetSymbolAddress((void**)&p_yhd, g_yhd);
    cudaGetSymbolAddress((void**)&p_yld, g_yld);
    cudaGetSymbolAddress((void**)&p_xh, g_xh);
    cudaGetSymbolAddress((void**)&p_xl, g_xl);
    cudaGetSymbolAddress((void**)&p_W0h, s_Whh0h);
    cudaGetSymbolAddress((void**)&p_W0l, s_Whh0l);
    cudaGetSymbolAddress((void**)&p_Wh, s_Whhh);
    cudaGetSymbolAddress((void**)&p_Wl, s_Whhl);
    cudaGetSymbolAddress((void**)&p_Wih_h, s_Wihh);
    cudaGetSymbolAddress((void**)&p_Wih_l, s_Wihl);
    cudaGetSymbolAddress((void**)&p_Wi0h, s_Wih0h);
    cudaGetSymbolAddress((void**)&p_Wi0l, s_Wih0l);
    cudaGetSymbolAddress((void**)&p_oWh, s_oWh);
    cudaGetSymbolAddress((void**)&p_oWl, s_oWl);

    // ---- prep: ONE merged launch (also puts enc_step at ncu capture slot 6) ----
    k_prep<<<1184, 256>>>(Whh0, Whh, dWhh, Wih, oW, Wih0, x);

    const dim3 gG(G3 / 64, BT / 128);
    const dim3 gE(H / 16, 2);
    const int  gDc = H2 / 16;

    // ---- encoder layer 0 (K = 80 padded) ----
    gemm_h2p<<<gG, 256>>>(p_xh, p_xl, DP, p_Wi0h,                 p_Wi0l,                 b0,        p_xg,      BT, G3, DP, G6);
    gemm_h2p<<<gG, 256>>>(p_xh, p_xl, DP, p_Wi0h + (size_t)G3*DP, p_Wi0l + (size_t)G3*DP, b0 + 2*G3, p_xg + G3, BT, G3, DP, G6);
    for (int t = 0; t < T; t++)
        enc_step_h5<<<gE, 384, SMEM_STEP>>>(p_W0h, p_W0l, b0 + G3, 2 * G3, p_yha, p_yla, t);

    // ---- encoder layer 1 ----
    gemm_h2p<<<gG, 256>>>(p_yha, p_yla, H2, p_Wih_h,                 p_Wih_l,                 bb,        p_xg,      BT, G3, H2, G6);
    gemm_h2p<<<gG, 256>>>(p_yha, p_yla, H2, p_Wih_h + (size_t)G3*H2, p_Wih_l + (size_t)G3*H2, bb + 2*G3, p_xg + G3, BT, G3, H2, G6);
    for (int t = 0; t < T; t++)
        enc_step_h5<<<gE, 384, SMEM_STEP>>>(p_Wh, p_Wl, bb + G3, 2 * G3, p_yhb, p_ylb, t);

    // ---- encoder layer 2 ----
    gemm_h2p<<<gG, 256>>>(p_yhb, p_ylb, H2, p_Wih_h + (size_t)2*G3*H2, p_Wih_l + (size_t)2*G3*H2, bb + 4*G3, p_xg,      BT, G3, H2, G6);
    gemm_h2p<<<gG, 256>>>(p_yhb, p_ylb, H2, p_Wih_h + (size_t)3*G3*H2, p_Wih_l + (size_t)3*G3*H2, bb + 6*G3, p_xg + G3, BT, G3, H2, G6);
    for (int t = 0; t < T; t++)
        enc_step_h5<<<gE, 384, SMEM_STEP>>>(p_Wh + (size_t)2*G3*H, p_Wl + (size_t)2*G3*H, bb + 5*G3, 2 * G3, p_yha, p_yla, t);

    // ---- gather (enc_hidden out + decoder ring seed) ----
    gather_kernel<<<(B * H2) / 256, 256>>>(p_yha, p_yla, slen, out);

    // ---- decoder scan ----
    for (int t = 0; t < T; t++)
        dec_step_h5<<<gDc, 384, SMEM_STEP>>>(db, db + G6, t);

    // ---- output projection ----
    gemm_h2p<<<dim3(2, BT / 128), 256>>>(p_yhd, p_yld, H2, p_oWh, p_oWl, ob,
                                         out + (size_t)B * H2, BT, D, H2, D);
}